// round 15
// baseline (speedup 1.0000x reference)
#include <cuda_runtime.h>
#include <cuda_fp16.h>
#include <cstdint>
#include <math.h>

#define N_NODES   20000
#define N_EDGES   320000
#define DIM       128
#define CODEBOOK_N 12000
#define CODEBOOK_PAD 12032
#define N_GRAPHS  256
#define N_LAYERS  5
#define BN_EPS    1e-5f
#define COMMIT_W  0.25f
#define STAT_BLOCKS 157
#define NODE_PAD  20032            // 313*64

// VQ: exact fp16 3-term product via pass pairing, 4-way codebook split.
#define VQ_K       256
#define VQ_TILES   188
#define VQ_CPT     4
#define VQ_SEGS    4
#define VQ_TPS     47
#define VQ_CPS     (VQ_TPS*VQ_CPT)
#define VQ_MBLK    313
#define VQ_MARGIN  0.02f
#define AS_STRIDE  264
#define BS_STRIDE  72
#define BS_BUF_H   (64*BS_STRIDE)

typedef unsigned long long ull;

// ---------------- scratch ----------------
__device__ float g_z [N_NODES*DIM];
__device__ float g_t2[N_NODES*DIM];
__device__ float g_h [N_NODES*DIM];
__device__ int   g_deg[N_NODES];
__device__ int   g_offs[N_NODES+1];
__device__ int   g_cursor[N_NODES];
__device__ ull   g_csrk[N_EDGES];   // (edge_idx<<32)|src — sorted per node = edge order
__device__ float g_pstats[STAT_BLOCKS*2*DIM];
__device__ float g_mean[DIM];
__device__ float g_invstd[DIM];
__device__ float g_cnorm[CODEBOOK_PAD];
__device__ int   g_idx[N_NODES];
__device__ float g_cacc[N_GRAPHS*DIM];
__device__ float g_sacc[N_GRAPHS*DIM];
__device__ float g_cmt[1];
__device__ __half g_cbs[(size_t)CODEBOOK_PAD * VQ_K];
__device__ float g_pd1[VQ_SEGS*NODE_PAD];
__device__ float g_pd2[VQ_SEGS*NODE_PAD];
__device__ int   g_pj1[VQ_SEGS*NODE_PAD];
__device__ int   g_flaglist[N_NODES];
__device__ int   g_flagcnt[1];
__device__ ull   g_best[N_NODES];

// ---------------- asm helpers ----------------
__device__ __forceinline__ uint32_t smem_u32(const void* p) {
    uint32_t a;
    asm("{ .reg .u64 t; cvta.to.shared.u64 t, %1; cvt.u32.u64 %0, t; }" : "=r"(a) : "l"(p));
    return a;
}
#define CP_ASYNC16(dst, src) \
    asm volatile("cp.async.cg.shared.global [%0], [%1], 16;" :: "r"(dst), "l"(src) : "memory")
#define CP_COMMIT() asm volatile("cp.async.commit_group;" ::: "memory")
#define CP_WAIT(n)  asm volatile("cp.async.wait_group %0;" :: "n"(n) : "memory")
#define LDSM4(r0,r1,r2,r3,addr) \
    asm volatile("ldmatrix.sync.aligned.m8n8.x4.shared.b16 {%0,%1,%2,%3}, [%4];" \
        : "=r"(r0), "=r"(r1), "=r"(r2), "=r"(r3) : "r"(addr))
#define MMA16816(d, a0,a1,a2,a3, b0,b1) \
    asm volatile("mma.sync.aligned.m16n8k16.row.col.f32.f16.f16.f32 " \
        "{%0,%1,%2,%3}, {%4,%5,%6,%7}, {%8,%9}, {%0,%1,%2,%3};" \
        : "+f"((d)[0]), "+f"((d)[1]), "+f"((d)[2]), "+f"((d)[3]) \
        : "r"(a0), "r"(a1), "r"(a2), "r"(a3), "r"(b0), "r"(b1))

__device__ __forceinline__ uint32_t fkey(float f) {
    uint32_t u = __float_as_uint(f);
    return (u & 0x80000000u) ? ~u : (u | 0x80000000u);
}
__device__ __forceinline__ void split16(float f, __half& hi, __half& lo) {
    hi = __float2half_rn(f);
    lo = __float2half_rn(f - __half2float(hi));
}

// ---------------- CSR build: edge-order deterministic ----------------------
__global__ void k_hist(const int* __restrict__ dst, int* __restrict__ deg) {
    int e = blockIdx.x * blockDim.x + threadIdx.x;
    if (e < N_EDGES) atomicAdd(&deg[dst[e]], 1);
}
__global__ void k_scan(const int* __restrict__ deg, int* __restrict__ offs) {
    __shared__ int sh[1024];
    __shared__ int carry;
    int tid = threadIdx.x;
    if (tid == 0) { carry = 0; offs[0] = 0; }
    __syncthreads();
    for (int base = 0; base < N_NODES; base += 1024) {
        int v = (base + tid < N_NODES) ? deg[base + tid] : 0;
        sh[tid] = v;
        __syncthreads();
        for (int o = 1; o < 1024; o <<= 1) {
            int t = (tid >= o) ? sh[tid - o] : 0;
            __syncthreads();
            sh[tid] += t;
            __syncthreads();
        }
        if (base + tid < N_NODES) offs[base + tid + 1] = carry + sh[tid];
        __syncthreads();
        if (tid == 0) carry += sh[1023];
        __syncthreads();
    }
}
__global__ void k_fill(const int* __restrict__ src, const int* __restrict__ dst,
                       int* __restrict__ cursor, ull* __restrict__ csrk) {
    int e = blockIdx.x * blockDim.x + threadIdx.x;
    if (e < N_EDGES) {
        int d = dst[e];
        int slot = atomicAdd(&cursor[d], 1);
        csrk[slot] = ((ull)(uint32_t)e << 32) | (uint32_t)src[e];
    }
}
__global__ void k_sortcsr(const int* __restrict__ offs, ull* __restrict__ csrk) {
    int n = blockIdx.x * blockDim.x + threadIdx.x;
    if (n >= N_NODES) return;
    int s = offs[n], e = offs[n + 1];
    for (int i = s + 1; i < e; i++) {
        ull v = csrk[i];
        int j = i - 1;
        while (j >= s && csrk[j] > v) { csrk[j + 1] = csrk[j]; j--; }
        csrk[j + 1] = v;
    }
}

// ---------------- aggregation: fp32, edge order (FROZEN math) -------------
__global__ void k_agg(const float* __restrict__ h, const int* __restrict__ offs,
                      const ull* __restrict__ csrk, float* __restrict__ z) {
    int warp = (blockIdx.x * blockDim.x + threadIdx.x) >> 5;
    int lane = threadIdx.x & 31;
    if (warp >= N_NODES) return;
    const float4* hv = (const float4*)h;
    float4 acc = hv[warp * 32 + lane];
    int s = offs[warp], e = offs[warp + 1];
    for (int i = s; i < e; i++) {
        int sidx = (int)(uint32_t)(__ldg(&csrk[i]) & 0xFFFFFFFFull);
        float4 v = hv[sidx * 32 + lane];
        acc.x += v.x; acc.y += v.y; acc.z += v.z; acc.w += v.w;
    }
    ((float4*)z)[warp * 32 + lane] = acc;
}

// agg with BN applied inline: summand = ((t2-mean)*invstd)*gamma + beta —
// identical expression tree to k_bnapply, so z is bitwise unchanged.
__global__ void k_agg_bn(const float* __restrict__ t2, const float* __restrict__ mean,
                         const float* __restrict__ invstd, const float* __restrict__ gamma,
                         const float* __restrict__ beta, const int* __restrict__ offs,
                         const ull* __restrict__ csrk, float* __restrict__ z) {
    int warp = (blockIdx.x * blockDim.x + threadIdx.x) >> 5;
    int lane = threadIdx.x & 31;
    if (warp >= N_NODES) return;
    const float4* tv = (const float4*)t2;
    float4 m  = ((const float4*)mean)[lane];
    float4 iv = ((const float4*)invstd)[lane];
    float4 gm = ((const float4*)gamma)[lane];
    float4 bt = ((const float4*)beta)[lane];
    float4 t = tv[warp * 32 + lane];
    float4 acc;
    acc.x = (t.x - m.x) * iv.x * gm.x + bt.x;
    acc.y = (t.y - m.y) * iv.y * gm.y + bt.y;
    acc.z = (t.z - m.z) * iv.z * gm.z + bt.z;
    acc.w = (t.w - m.w) * iv.w * gm.w + bt.w;
    int s = offs[warp], e = offs[warp + 1];
    for (int i = s; i < e; i++) {
        int sidx = (int)(uint32_t)(__ldg(&csrk[i]) & 0xFFFFFFFFull);
        float4 v = tv[sidx * 32 + lane];
        acc.x += (v.x - m.x) * iv.x * gm.x + bt.x;
        acc.y += (v.y - m.y) * iv.y * gm.y + bt.y;
        acc.z += (v.z - m.z) * iv.z * gm.z + bt.z;
        acc.w += (v.w - m.w) * iv.w * gm.w + bt.w;
    }
    ((float4*)z)[warp * 32 + lane] = acc;
}

// ---------------- fused dual GEMM (FROZEN math): t2 = relu(relu(zW1+b1)W2+b2)
__global__ __launch_bounds__(256, 3) void k_gemm_fused(
        const float* __restrict__ A, const float* __restrict__ W1,
        const float* __restrict__ b1, const float* __restrict__ W2,
        const float* __restrict__ b2, float* __restrict__ out) {
    __shared__ float As[32][128];
    __shared__ float Ws[32][128];
    int tid = threadIdx.x;
    int tx = tid & 31, ty = tid >> 5;
    int row0 = blockIdx.x * 32;
    float acc[4][4];

#pragma unroll
    for (int it = 0; it < 4; it++) {
        int i = tid + it * 256;
        int r = i >> 5, c4 = i & 31;
        *(float4*)&As[r][c4 * 4] = *(const float4*)&A[(size_t)(row0 + r) * DIM + c4 * 4];
    }

#pragma unroll
    for (int r = 0; r < 4; r++)
#pragma unroll
        for (int c = 0; c < 4; c++) acc[r][c] = 0.f;
    for (int kt = 0; kt < DIM; kt += 32) {
#pragma unroll
        for (int it = 0; it < 4; it++) {
            int i = tid + it * 256;
            int r = i >> 5, c4 = i & 31;
            *(float4*)&Ws[r][c4 * 4] = *(const float4*)&W1[(size_t)(kt + r) * DIM + c4 * 4];
        }
        __syncthreads();
#pragma unroll
        for (int k = 0; k < 32; k++) {
            float4 w = *(float4*)&Ws[k][tx * 4];
#pragma unroll
            for (int r = 0; r < 4; r++) {
                float a = As[ty * 4 + r][kt + k];
                acc[r][0] += a * w.x;
                acc[r][1] += a * w.y;
                acc[r][2] += a * w.z;
                acc[r][3] += a * w.w;
            }
        }
        __syncthreads();
    }
    {
        float4 b = *(const float4*)&b1[tx * 4];
        __syncthreads();
#pragma unroll
        for (int r = 0; r < 4; r++) {
            float v0 = fmaxf(acc[r][0] + b.x, 0.f);
            float v1 = fmaxf(acc[r][1] + b.y, 0.f);
            float v2 = fmaxf(acc[r][2] + b.z, 0.f);
            float v3 = fmaxf(acc[r][3] + b.w, 0.f);
            *(float4*)&As[ty * 4 + r][tx * 4] = make_float4(v0, v1, v2, v3);
        }
        __syncthreads();
    }

#pragma unroll
    for (int r = 0; r < 4; r++)
#pragma unroll
        for (int c = 0; c < 4; c++) acc[r][c] = 0.f;
    for (int kt = 0; kt < DIM; kt += 32) {
#pragma unroll
        for (int it = 0; it < 4; it++) {
            int i = tid + it * 256;
            int r = i >> 5, c4 = i & 31;
            *(float4*)&Ws[r][c4 * 4] = *(const float4*)&W2[(size_t)(kt + r) * DIM + c4 * 4];
        }
        __syncthreads();
#pragma unroll
        for (int k = 0; k < 32; k++) {
            float4 w = *(float4*)&Ws[k][tx * 4];
#pragma unroll
            for (int r = 0; r < 4; r++) {
                float a = As[ty * 4 + r][kt + k];
                acc[r][0] += a * w.x;
                acc[r][1] += a * w.y;
                acc[r][2] += a * w.z;
                acc[r][3] += a * w.w;
            }
        }
        __syncthreads();
    }
    {
        float4 b = *(const float4*)&b2[tx * 4];
#pragma unroll
        for (int r = 0; r < 4; r++) {
            int row = row0 + ty * 4 + r;
            float v0 = fmaxf(acc[r][0] + b.x, 0.f);
            float v1 = fmaxf(acc[r][1] + b.y, 0.f);
            float v2 = fmaxf(acc[r][2] + b.z, 0.f);
            float v3 = fmaxf(acc[r][3] + b.w, 0.f);
            *(float4*)&out[(size_t)row * DIM + tx * 4] = make_float4(v0, v1, v2, v3);
        }
    }
}

// ---------------- head GEMM fp32 (FROZEN, small M) -------------------------
__global__ __launch_bounds__(256) void k_gemm(
        const float* __restrict__ A, const float* __restrict__ W,
        const float* __restrict__ bias, float* __restrict__ out,
        int M, int doRelu) {
    __shared__ float As[64][32];
    __shared__ float Ws[32][128];
    int tid = threadIdx.x;
    int tx = tid & 31, ty = tid >> 5;
    int row0 = blockIdx.x * 64;
    float acc[8][4];
#pragma unroll
    for (int r = 0; r < 8; r++)
#pragma unroll
        for (int c = 0; c < 4; c++) acc[r][c] = 0.f;

    for (int kt = 0; kt < DIM; kt += 32) {
#pragma unroll
        for (int it = 0; it < 2; it++) {
            int i = tid + it * 256;
            int r = i >> 3, c4 = i & 7;
            int row = row0 + r;
            float4 v = make_float4(0.f, 0.f, 0.f, 0.f);
            if (row < M) v = *(const float4*)&A[row * DIM + kt + c4 * 4];
            *(float4*)&As[r][c4 * 4] = v;
        }
#pragma unroll
        for (int it = 0; it < 4; it++) {
            int i = tid + it * 256;
            int r = i >> 5, c4 = i & 31;
            *(float4*)&Ws[r][c4 * 4] = *(const float4*)&W[(kt + r) * DIM + c4 * 4];
        }
        __syncthreads();
#pragma unroll
        for (int k = 0; k < 32; k++) {
            float4 w = *(float4*)&Ws[k][tx * 4];
#pragma unroll
            for (int r = 0; r < 8; r++) {
                float a = As[ty * 8 + r][k];
                acc[r][0] += a * w.x;
                acc[r][1] += a * w.y;
                acc[r][2] += a * w.z;
                acc[r][3] += a * w.w;
            }
        }
        __syncthreads();
    }
    float4 b = *(const float4*)&bias[tx * 4];
#pragma unroll
    for (int r = 0; r < 8; r++) {
        int row = row0 + ty * 8 + r;
        if (row < M) {
            float v0 = acc[r][0] + b.x;
            float v1 = acc[r][1] + b.y;
            float v2 = acc[r][2] + b.z;
            float v3 = acc[r][3] + b.w;
            if (doRelu) {
                v0 = fmaxf(v0, 0.f); v1 = fmaxf(v1, 0.f);
                v2 = fmaxf(v2, 0.f); v3 = fmaxf(v3, 0.f);
            }
            *(float4*)&out[row * DIM + tx * 4] = make_float4(v0, v1, v2, v3);
        }
    }
}

// ---------------- BN stats (FROZEN) ---------------------------------------
__global__ void k_stats(const float* __restrict__ t2, float* __restrict__ pstats) {
    __shared__ float ss[256], qq[256];
    int tid = threadIdx.x;
    int col = tid & 127, half = tid >> 7;
    float s = 0.f, q = 0.f;
    int row0 = blockIdx.x * 128;
    for (int i = half; i < 128; i += 2) {
        int r = row0 + i;
        if (r < N_NODES) {
            float v = t2[(size_t)r * DIM + col];
            s += v; q += v * v;
        }
    }
    ss[tid] = s; qq[tid] = q;
    __syncthreads();
    if (tid < 128) {
        pstats[blockIdx.x * 256 + tid]       = ss[tid] + ss[tid + 128];
        pstats[blockIdx.x * 256 + 128 + tid] = qq[tid] + qq[tid + 128];
    }
}

__global__ void k_bnfin(const float* __restrict__ pstats,
                        float* __restrict__ mean, float* __restrict__ invstd) {
    int d = threadIdx.x;
    float s = 0.f, q = 0.f;
    for (int b = 0; b < STAT_BLOCKS; b++) {
        s += pstats[b * 256 + d];
        q += pstats[b * 256 + 128 + d];
    }
    float mu = s / (float)N_NODES;
    float var = q / (float)N_NODES - mu * mu;
    mean[d] = mu;
    invstd[d] = rsqrtf(var + BN_EPS);
}

__global__ void k_bnapply(const float* __restrict__ z, const float* __restrict__ mean,
                          const float* __restrict__ invstd, const float* __restrict__ gamma,
                          const float* __restrict__ beta, float* __restrict__ h) {
    int i = blockIdx.x * blockDim.x + threadIdx.x;
    if (i < N_NODES * DIM) {
        int d = i & (DIM - 1);
        h[i] = (z[i] - mean[d]) * invstd[d] * gamma[d] + beta[d];
    }
}

// ---------------- codebook prep: norms + fp16 split, one pass -------------
// warp per code; norm reduction order identical to old k_cnorm (bitwise same).
__global__ void k_cbprep(const float* __restrict__ cb, float* __restrict__ cnorm,
                         __half* __restrict__ cbs) {
    int warp = (blockIdx.x * blockDim.x + threadIdx.x) >> 5;
    int lane = threadIdx.x & 31;
    if (warp >= CODEBOOK_PAD) return;
    __half* row = cbs + (size_t)warp * VQ_K;
    if (warp >= CODEBOOK_N) {
        if (lane == 0) cnorm[warp] = 1e30f;
        *(ull*)&row[lane * 4] = 0ull;
        *(ull*)&row[128 + lane * 4] = 0ull;
        return;
    }
    float4 v = ((const float4*)cb)[warp * 32 + lane];
    // split
    __half hx, lx, hy, ly, hz, lz, hw, lw;
    split16(v.x, hx, lx); split16(v.y, hy, ly);
    split16(v.z, hz, lz); split16(v.w, hw, lw);
    row[lane * 4 + 0] = hx; row[lane * 4 + 1] = hy;
    row[lane * 4 + 2] = hz; row[lane * 4 + 3] = hw;
    row[128 + lane * 4 + 0] = lx; row[128 + lane * 4 + 1] = ly;
    row[128 + lane * 4 + 2] = lz; row[128 + lane * 4 + 3] = lw;
    // norm (same order as before)
    float s = v.x * v.x + v.y * v.y + v.z * v.z + v.w * v.w;
#pragma unroll
    for (int o = 16; o; o >>= 1) s += __shfl_xor_sync(0xffffffffu, s, o);
    if (lane == 0) cnorm[warp] = s;
}

// ---------------- VQ main: segment-split fp16 3-term GEMM-argmin -----------
__global__ __launch_bounds__(256, 2) void k_vq_mma(
        const float* __restrict__ h, const __half* __restrict__ cbs,
        const float* __restrict__ cnorm,
        float* __restrict__ pd1, float* __restrict__ pd2, int* __restrict__ pj1) {
    extern __shared__ __align__(16) char dyn[];
    __half* As = (__half*)dyn;                 // [64][264]
    __half* Bs = As + 64 * AS_STRIDE;          // [4][64][72]
    float* cns = (float*)(Bs + 4 * BS_BUF_H);  // [64]
    float* rD1 = cns + 64;                     // [64][4]
    float* rD2 = rD1 + 256;
    int*   rJ1 = (int*)(rD2 + 256);
    uint32_t As_u = smem_u32(As);
    uint32_t Bs_u = smem_u32(Bs);

    int tid = threadIdx.x, lane = tid & 31, wid = tid >> 5;
    int warp_m = wid & 1, warp_n = wid >> 1;   // 2m x 4n
    int node0 = blockIdx.x * 64;
    int seg = blockIdx.y;
    int cstart = seg * VQ_CPS;
    int cend = cstart + VQ_CPS;

    {
        int r = tid >> 2, q = tid & 3;
        bool valid = (node0 + r) < N_NODES;
        const float4* hp = (const float4*)(h + (size_t)(valid ? node0 + r : 0) * DIM);
        __half* arow = As + r * AS_STRIDE;
#pragma unroll
        for (int v = 0; v < 8; v++) {
            float4 f = valid ? hp[q * 8 + v] : make_float4(0.f, 0.f, 0.f, 0.f);
            __half hx, lx, hy, ly, hz, lz, hw, lw;
            split16(f.x, hx, lx); split16(f.y, hy, ly);
            split16(f.z, hz, lz); split16(f.w, hw, lw);
            int col = q * 32 + v * 4;
            arow[col + 0] = hx; arow[col + 1] = hy; arow[col + 2] = hz; arow[col + 3] = hw;
            arow[128 + col + 0] = lx; arow[128 + col + 1] = ly;
            arow[128 + col + 2] = lz; arow[128 + col + 3] = lw;
        }
    }

#pragma unroll
    for (int pc = 0; pc < 2; pc++) {
        int ci = cstart + pc;
        const __half* base = cbs + (size_t)(ci >> 2) * 64 * VQ_K + (ci & 3) * 64;
#pragma unroll
        for (int it = 0; it < 2; it++) {
            int i = tid + it * 256;
            int row = i >> 3, c16 = i & 7;
            CP_ASYNC16(Bs_u + (uint32_t)(pc * BS_BUF_H + row * BS_STRIDE + c16 * 8) * 2,
                       base + (size_t)row * VQ_K + c16 * 8);
        }
        CP_COMMIT();
    }

    float d1v[2][2] = {{1e38f, 1e38f}, {1e38f, 1e38f}};
    float d2v[2][2] = {{1e38f, 1e38f}, {1e38f, 1e38f}};
    int   j1v[2][2] = {{0, 0}, {0, 0}};
    int lr = lane & 7, g = lane >> 3;
    float acc[2][2][4];

    for (int ci = cstart; ci < cend; ci++) {
        int t = ci >> 2, c = ci & 3;
        int buf = ci & 3;
        if (c == 0) {
#pragma unroll
            for (int mt = 0; mt < 2; mt++)
#pragma unroll
                for (int hf = 0; hf < 2; hf++)
#pragma unroll
                    for (int r = 0; r < 4; r++) acc[mt][hf][r] = 0.f;
        }
        if (ci + 2 < cend) {
            int pidx = ci + 2;
            int pbuf = pidx & 3;
            const __half* base = cbs + (size_t)(pidx >> 2) * 64 * VQ_K + (pidx & 3) * 64;
#pragma unroll
            for (int it = 0; it < 2; it++) {
                int i = tid + it * 256;
                int row = i >> 3, c16 = i & 7;
                CP_ASYNC16(Bs_u + (uint32_t)(pbuf * BS_BUF_H + row * BS_STRIDE + c16 * 8) * 2,
                           base + (size_t)row * VQ_K + c16 * 8);
            }
            CP_COMMIT();
            CP_WAIT(2);
        } else {
            CP_WAIT(0);
        }
        __syncthreads();
        if (c == 0 && tid < 64) cns[tid] = __ldg(&cnorm[t * 64 + tid]);

        uint32_t bbase = Bs_u + (uint32_t)(buf * BS_BUF_H) * 2;
        if (c < 2) {
#pragma unroll
            for (int kk = 0; kk < 4; kk++) {
                int kcol = c * 64 + kk * 16;
                uint32_t ah0[2], ah1[2], ah2[2], ah3[2];
                uint32_t al0[2], al1[2], al2[2], al3[2];
#pragma unroll
                for (int mt = 0; mt < 2; mt++) {
                    uint32_t abase = As_u +
                        (uint32_t)((warp_m * 32 + mt * 16 + lr + ((g & 1) << 3)) * AS_STRIDE
                                   + kcol + ((g >> 1) << 3)) * 2;
                    LDSM4(ah0[mt], ah1[mt], ah2[mt], ah3[mt], abase);
                    LDSM4(al0[mt], al1[mt], al2[mt], al3[mt], abase + 128 * 2);
                }
                uint32_t b0, b1, b2, b3;
                uint32_t baddr = bbase +
                    (uint32_t)((warp_n * 16 + lr + ((g >> 1) << 3)) * BS_STRIDE
                               + kk * 16 + ((g & 1) << 3)) * 2;
                LDSM4(b0, b1, b2, b3, baddr);
#pragma unroll
                for (int mt = 0; mt < 2; mt++) {
                    MMA16816(acc[mt][0], ah0[mt], ah1[mt], ah2[mt], ah3[mt], b0, b1);
                    MMA16816(acc[mt][1], ah0[mt], ah1[mt], ah2[mt], ah3[mt], b2, b3);
                    MMA16816(acc[mt][0], al0[mt], al1[mt], al2[mt], al3[mt], b0, b1);
                    MMA16816(acc[mt][1], al0[mt], al1[mt], al2[mt], al3[mt], b2, b3);
                }
            }
        } else {
            int cc = c - 2;
#pragma unroll
            for (int kk = 0; kk < 4; kk++) {
                int kcol = cc * 64 + kk * 16;
                uint32_t ah0[2], ah1[2], ah2[2], ah3[2];
#pragma unroll
                for (int mt = 0; mt < 2; mt++) {
                    uint32_t abase = As_u +
                        (uint32_t)((warp_m * 32 + mt * 16 + lr + ((g & 1) << 3)) * AS_STRIDE
                                   + kcol + ((g >> 1) << 3)) * 2;
                    LDSM4(ah0[mt], ah1[mt], ah2[mt], ah3[mt], abase);
                }
                uint32_t b0, b1, b2, b3;
                uint32_t baddr = bbase +
                    (uint32_t)((warp_n * 16 + lr + ((g >> 1) << 3)) * BS_STRIDE
                               + kk * 16 + ((g & 1) << 3)) * 2;
                LDSM4(b0, b1, b2, b3, baddr);
#pragma unroll
                for (int mt = 0; mt < 2; mt++) {
                    MMA16816(acc[mt][0], ah0[mt], ah1[mt], ah2[mt], ah3[mt], b0, b1);
                    MMA16816(acc[mt][1], ah0[mt], ah1[mt], ah2[mt], ah3[mt], b2, b3);
                }
            }
        }

        if (c == VQ_CPT - 1) {
            int cb0 = warp_n * 16;
            int lcol = 2 * (lane & 3);
#pragma unroll
            for (int hf = 0; hf < 2; hf++) {
                int cloc = cb0 + hf * 8 + lcol;
                float cn0 = cns[cloc], cn1 = cns[cloc + 1];
                int code = t * 64 + cloc;
#pragma unroll
                for (int mt = 0; mt < 2; mt++)
#pragma unroll
                    for (int rs = 0; rs < 2; rs++) {
                        float dA = cn0 - 2.f * acc[mt][hf][rs * 2 + 0];
                        float dB = cn1 - 2.f * acc[mt][hf][rs * 2 + 1];
                        if (dA < d1v[mt][rs]) { d2v[mt][rs] = d1v[mt][rs]; d1v[mt][rs] = dA; j1v[mt][rs] = code; }
                        else if (dA < d2v[mt][rs]) d2v[mt][rs] = dA;
                        if (dB < d1v[mt][rs]) { d2v[mt][rs] = d1v[mt][rs]; d1v[mt][rs] = dB; j1v[mt][rs] = code + 1; }
                        else if (dB < d2v[mt][rs]) d2v[mt][rs] = dB;
                    }
            }
        }
    }

#pragma unroll
    for (int o = 1; o <= 2; o <<= 1) {
#pragma unroll
        for (int mt = 0; mt < 2; mt++)
#pragma unroll
            for (int rs = 0; rs < 2; rs++) {
                float od1 = __shfl_xor_sync(0xffffffffu, d1v[mt][rs], o);
                float od2 = __shfl_xor_sync(0xffffffffu, d2v[mt][rs], o);
                int   oj  = __shfl_xor_sync(0xffffffffu, j1v[mt][rs], o);
                if (od1 < d1v[mt][rs] || (od1 == d1v[mt][rs] && oj < j1v[mt][rs])) {
                    d2v[mt][rs] = fminf(d1v[mt][rs], od2);
                    d1v[mt][rs] = od1; j1v[mt][rs] = oj;
                } else {
                    d2v[mt][rs] = fminf(d2v[mt][rs], od1);
                }
            }
    }
    __syncthreads();
    if ((lane & 3) == 0) {
#pragma unroll
        for (int mt = 0; mt < 2; mt++)
#pragma unroll
            for (int rs = 0; rs < 2; rs++) {
                int nl = warp_m * 32 + mt * 16 + rs * 8 + (lane >> 2);
                rD1[nl * 4 + warp_n] = d1v[mt][rs];
                rD2[nl * 4 + warp_n] = d2v[mt][rs];
                rJ1[nl * 4 + warp_n] = j1v[mt][rs];
            }
    }
    __syncthreads();
    if (tid < 64) {
        float f1 = rD1[tid * 4], f2 = rD2[tid * 4];
        int fj = rJ1[tid * 4];
#pragma unroll
        for (int wn = 1; wn < 4; wn++) {
            float b1 = rD1[tid * 4 + wn], b2 = rD2[tid * 4 + wn];
            int bj = rJ1[tid * 4 + wn];
            if (b1 < f1 || (b1 == f1 && bj < fj)) {
                f2 = fminf(f1, b2); f1 = b1; fj = bj;
            } else {
                f2 = fminf(f2, b1);
            }
        }
        int slot = seg * NODE_PAD + node0 + tid;
        pd1[slot] = f1; pd2[slot] = f2; pj1[slot] = fj;
    }
}

// ---------------- merge segments (deterministic, fixed order) --------------
__global__ void k_vqmerge(const float* __restrict__ pd1, const float* __restrict__ pd2,
                          const int* __restrict__ pj1, int* __restrict__ outidx,
                          int* __restrict__ flaglist, int* __restrict__ flagcnt) {
    int n = blockIdx.x * blockDim.x + threadIdx.x;
    if (n >= N_NODES) return;
    float f1 = pd1[n], f2 = pd2[n];
    int fj = pj1[n];
#pragma unroll
    for (int s = 1; s < VQ_SEGS; s++) {
        float b1 = pd1[s * NODE_PAD + n], b2 = pd2[s * NODE_PAD + n];
        int bj = pj1[s * NODE_PAD + n];
        if (b1 < f1 || (b1 == f1 && bj < fj)) {
            f2 = fminf(f1, b2); f1 = b1; fj = bj;
        } else {
            f2 = fminf(f2, b1);
        }
    }
    outidx[n] = fj;
    if (f2 - f1 < VQ_MARGIN) {
        int p = atomicAdd(flagcnt, 1);
        flaglist[p] = n;
    }
}

// ---------------- exact fp32 rescue (order-invariant via atomicMin) --------
__global__ __launch_bounds__(128) void k_rescue(
        const float* __restrict__ h, const float* __restrict__ cb,
        const float* __restrict__ cnorm, const int* __restrict__ flaglist,
        const int* __restrict__ flagcnt, ull* __restrict__ best) {
    extern __shared__ __align__(16) float rs[];
    float* cs   = rs;
    float* hrow = cs + 128 * 128;
    float* rd   = hrow + 128;
    int*   rj   = (int*)(rd + 128);
    int tid = threadIdx.x;
    int c0 = blockIdx.x * 128;
    int code = c0 + tid;
#pragma unroll
    for (int it = 0; it < 32; it++) {
        int i = tid + it * 128;
        int row = i >> 5, c4 = i & 31;
        float4 v = make_float4(0.f, 0.f, 0.f, 0.f);
        if (c0 + row < CODEBOOK_N) v = __ldg(&((const float4*)cb)[(size_t)(c0 + row) * 32 + c4]);
        *(float4*)&cs[row * 128 + c4 * 4] = v;
    }
    float cn = cnorm[code];
    __syncthreads();
    int cnt = *flagcnt;
    const float4* crow4 = (const float4*)&cs[tid * 128];
    const float4* h4 = (const float4*)hrow;
    for (int f = 0; f < cnt; f++) {
        int node = flaglist[f];
        if (tid < 32) ((float4*)hrow)[tid] = ((const float4*)(h + (size_t)node * DIM))[tid];
        __syncthreads();
        float dot = 0.f;
#pragma unroll
        for (int k4 = 0; k4 < 32; k4++) {
            int i = (k4 + tid) & 31;
            float4 cv = crow4[i];
            float4 hv = h4[i];
            dot += cv.x * hv.x + cv.y * hv.y + cv.z * hv.z + cv.w * hv.w;
        }
        float d = cn - 2.f * dot;
        rd[tid] = d; rj[tid] = code;
        __syncthreads();
        for (int o = 64; o; o >>= 1) {
            if (tid < o) {
                float od = rd[tid + o]; int oc = rj[tid + o];
                if (od < rd[tid] || (od == rd[tid] && oc < rj[tid])) {
                    rd[tid] = od; rj[tid] = oc;
                }
            }
            __syncthreads();
        }
        if (tid == 0) {
            ull key = ((ull)fkey(rd[0]) << 32) | (uint32_t)rj[0];
            atomicMin(&best[node], key);
        }
        __syncthreads();
    }
}

__global__ void k_flagapply(const int* __restrict__ flaglist, const int* __restrict__ flagcnt,
                            const ull* __restrict__ best, int* __restrict__ outidx) {
    int cnt = *flagcnt;
    for (int i = blockIdx.x * blockDim.x + threadIdx.x; i < cnt; i += gridDim.x * blockDim.x) {
        int node = flaglist[i];
        outidx[node] = (int)(best[node] & 0xFFFFFFFFull);
    }
}

// ---------------- final per-node ----------------
__global__ void k_final(const float* __restrict__ h, const float* __restrict__ cb,
                        const int* __restrict__ idx, const float* __restrict__ score,
                        const int* __restrict__ batch, float* __restrict__ cacc,
                        float* __restrict__ sacc, float* __restrict__ cmt) {
    __shared__ float sh[256];
    int i = blockIdx.x * blockDim.x + threadIdx.x;
    float local = 0.f;
    if (i < N_NODES * DIM) {
        int node = i >> 7, d = i & 127;
        float hv = h[i];
        float q = cb[idx[node] * DIM + d];
        float diff = q - hv;
        local = diff * diff;
        float res = hv + q;
        float sc = score[node];
        int b = batch[node];
        atomicAdd(&cacc[b * DIM + d], res * sc);
        atomicAdd(&sacc[b * DIM + d], res * (1.f - sc));
    }
    sh[threadIdx.x] = local;
    __syncthreads();
    for (int o = 128; o; o >>= 1) {
        if (threadIdx.x < o) sh[threadIdx.x] += sh[threadIdx.x + o];
        __syncthreads();
    }
    if (threadIdx.x == 0) atomicAdd(cmt, sh[0]);
}

__global__ void k_cmtfin(const float* __restrict__ cmt, float* __restrict__ out) {
    out[2 * N_GRAPHS * DIM] = COMMIT_W * cmt[0] / (float)(N_NODES * DIM);
}

// ---------------- launcher ----------------
extern "C" void kernel_launch(void* const* d_in, const int* in_sizes, int n_in,
                              void* d_out, int out_size) {
    const float* x        = (const float*)d_in[0];
    const int*   ei       = (const int*)  d_in[1];
    const int*   batch    = (const int*)  d_in[2];
    const float* score    = (const float*)d_in[3];
    const float* cW1      = (const float*)d_in[4];
    const float* cb1      = (const float*)d_in[5];
    const float* cW2      = (const float*)d_in[6];
    const float* cb2      = (const float*)d_in[7];
    const float* bng      = (const float*)d_in[8];
    const float* bnb      = (const float*)d_in[9];
    const float* codebook = (const float*)d_in[10];
    const float* fc1W     = (const float*)d_in[11];
    const float* fc1b     = (const float*)d_in[12];
    const float* fc2W     = (const float*)d_in[13];
    const float* fc2b     = (const float*)d_in[14];
    float* out = (float*)d_out;
    const int* src = ei;
    const int* dst = ei + N_EDGES;

    void *p_z, *p_t2, *p_h, *p_deg, *p_offs, *p_cursor, *p_csrk;
    void *p_pstats, *p_mean, *p_invstd, *p_cnorm, *p_idx, *p_cacc, *p_sacc, *p_cmt;
    void *p_cbs, *p_pd1, *p_pd2, *p_pj1, *p_flag, *p_fcnt, *p_best;
    cudaGetSymbolAddress(&p_z, g_z);
    cudaGetSymbolAddress(&p_t2, g_t2);
    cudaGetSymbolAddress(&p_h, g_h);
    cudaGetSymbolAddress(&p_deg, g_deg);
    cudaGetSymbolAddress(&p_offs, g_offs);
    cudaGetSymbolAddress(&p_cursor, g_cursor);
    cudaGetSymbolAddress(&p_csrk, g_csrk);
    cudaGetSymbolAddress(&p_pstats, g_pstats);
    cudaGetSymbolAddress(&p_mean, g_mean);
    cudaGetSymbolAddress(&p_invstd, g_invstd);
    cudaGetSymbolAddress(&p_cnorm, g_cnorm);
    cudaGetSymbolAddress(&p_idx, g_idx);
    cudaGetSymbolAddress(&p_cacc, g_cacc);
    cudaGetSymbolAddress(&p_sacc, g_sacc);
    cudaGetSymbolAddress(&p_cmt, g_cmt);
    cudaGetSymbolAddress(&p_cbs, g_cbs);
    cudaGetSymbolAddress(&p_pd1, g_pd1);
    cudaGetSymbolAddress(&p_pd2, g_pd2);
    cudaGetSymbolAddress(&p_pj1, g_pj1);
    cudaGetSymbolAddress(&p_flag, g_flaglist);
    cudaGetSymbolAddress(&p_fcnt, g_flagcnt);
    cudaGetSymbolAddress(&p_best, g_best);

    const int SMEM_VQ = 64 * AS_STRIDE * 2 + 4 * BS_BUF_H * 2 + 64 * 4 + 256 * 4 * 3;
    const int SMEM_RESCUE = 128 * 128 * 4 + 128 * 4 * 3;
    static bool attr_set = false;
    if (!attr_set) {
        cudaFuncSetAttribute(k_vq_mma, cudaFuncAttributeMaxDynamicSharedMemorySize, SMEM_VQ);
        cudaFuncSetAttribute(k_rescue, cudaFuncAttributeMaxDynamicSharedMemorySize, SMEM_RESCUE);
        attr_set = true;
    }

    // CSR build, canonicalized to exact EDGE order (FROZEN)
    cudaMemsetAsync(p_deg, 0, N_NODES * sizeof(int));
    k_hist<<<(N_EDGES + 255) / 256, 256>>>(dst, (int*)p_deg);
    k_scan<<<1, 1024>>>((const int*)p_deg, (int*)p_offs);
    cudaMemcpyAsync(p_cursor, p_offs, N_NODES * sizeof(int), cudaMemcpyDeviceToDevice);
    k_fill<<<(N_EDGES + 255) / 256, 256>>>(src, dst, (int*)p_cursor, (ull*)p_csrk);
    k_sortcsr<<<(N_NODES + 127) / 128, 128>>>((const int*)p_offs, (ull*)p_csrk);

    // codebook prep (one pass: norm + fp16 split)
    k_cbprep<<<(CODEBOOK_PAD * 32 + 255) / 256, 256>>>(codebook, (float*)p_cnorm,
                                                       (__half*)p_cbs);

    // MLP chain: BN fused into next layer's aggregation (h-bitwise invariant)
    k_agg<<<(N_NODES * 32 + 255) / 256, 256>>>(x, (const int*)p_offs,
                                               (const ull*)p_csrk, (float*)p_z);
    for (int l = 0; l < N_LAYERS; l++) {
        k_gemm_fused<<<N_NODES / 32, 256>>>(
            (const float*)p_z, cW1 + l * DIM * DIM, cb1 + l * DIM,
            cW2 + l * DIM * DIM, cb2 + l * DIM, (float*)p_t2);
        k_stats<<<STAT_BLOCKS, 256>>>((const float*)p_t2, (float*)p_pstats);
        k_bnfin<<<1, 128>>>((const float*)p_pstats, (float*)p_mean, (float*)p_invstd);
        if (l + 1 < N_LAYERS) {
            k_agg_bn<<<(N_NODES * 32 + 255) / 256, 256>>>(
                (const float*)p_t2, (const float*)p_mean, (const float*)p_invstd,
                bng + l * DIM, bnb + l * DIM, (const int*)p_offs,
                (const ull*)p_csrk, (float*)p_z);
        } else {
            k_bnapply<<<(N_NODES * DIM + 255) / 256, 256>>>(
                (const float*)p_t2, (const float*)p_mean, (const float*)p_invstd,
                bng + l * DIM, bnb + l * DIM, (float*)p_h);
        }
    }

    // VQ: segment-split tensor-core search + deterministic merge + exact rescue
    cudaMemsetAsync(p_fcnt, 0, sizeof(int));
    cudaMemsetAsync(p_best, 0xFF, N_NODES * sizeof(ull));
    k_vq_mma<<<dim3(VQ_MBLK, VQ_SEGS), 256, SMEM_VQ>>>(
        (const float*)p_h, (const __half*)p_cbs, (const float*)p_cnorm,
        (float*)p_pd1, (float*)p_pd2, (int*)p_pj1);
    k_vqmerge<<<(N_NODES + 255) / 256, 256>>>(
        (const float*)p_pd1, (const float*)p_pd2, (const int*)p_pj1,
        (int*)p_idx, (int*)p_flag, (int*)p_fcnt);
    k_rescue<<<CODEBOOK_PAD / 128, 128, SMEM_RESCUE>>>(
        (const float*)p_h, codebook, (const float*)p_cnorm,
        (const int*)p_flag, (const int*)p_fcnt, (ull*)p_best);
    k_flagapply<<<40, 256>>>((const int*)p_flag, (const int*)p_fcnt,
                             (const ull*)p_best, (int*)p_idx);

    cudaMemsetAsync(p_cacc, 0, N_GRAPHS * DIM * sizeof(float));
    cudaMemsetAsync(p_sacc, 0, N_GRAPHS * DIM * sizeof(float));
    cudaMemsetAsync(p_cmt, 0, sizeof(float));
    k_final<<<(N_NODES * DIM + 255) / 256, 256>>>(
        (const float*)p_h, codebook, (const int*)p_idx, score, batch,
        (float*)p_cacc, (float*)p_sacc, (float*)p_cmt);

    k_gemm<<<(N_GRAPHS + 63) / 64, 256>>>((const float*)p_cacc, fc1W, fc1b,
                                          out, N_GRAPHS, 1);
    k_gemm<<<(N_GRAPHS + 63) / 64, 256>>>((const float*)p_sacc, fc2W, fc2b,
                                          out + N_GRAPHS * DIM, N_GRAPHS, 1);
    k_cmtfin<<<1, 1>>>((const float*)p_cmt, out);
}

// round 16
// speedup vs baseline: 1.5038x; 1.5038x over previous
#include <cuda_runtime.h>
#include <cuda_fp16.h>
#include <cstdint>
#include <math.h>

#define N_NODES   20000
#define N_EDGES   320000
#define DIM       128
#define CODEBOOK_N 12000
#define CODEBOOK_PAD 12032
#define N_GRAPHS  256
#define N_LAYERS  5
#define BN_EPS    1e-5f
#define COMMIT_W  0.25f
#define STAT_BLOCKS 157
#define NODE_PAD  20032            // 313*64

// VQ: exact fp16 3-term product via pass pairing, 4-way codebook split.
#define VQ_K       256
#define VQ_TILES   188
#define VQ_CPT     4
#define VQ_SEGS    4
#define VQ_TPS     47
#define VQ_CPS     (VQ_TPS*VQ_CPT)
#define VQ_MBLK    313
#define VQ_MARGIN  0.02f
#define AS_STRIDE  264
#define BS_STRIDE  72
#define BS_BUF_H   (64*BS_STRIDE)

typedef unsigned long long ull;

// ---------------- scratch ----------------
__device__ float g_z [N_NODES*DIM];
__device__ float g_t2[N_NODES*DIM];
__device__ float g_h [N_NODES*DIM];
__device__ int   g_deg[N_NODES];
__device__ int   g_offs[N_NODES+1];
__device__ int   g_cursor[N_NODES];
__device__ ull   g_csrk[N_EDGES];   // (edge_idx<<32)|src — sorted per node = edge order
__device__ float g_pstats[STAT_BLOCKS*2*DIM];
__device__ float g_mean[DIM];
__device__ float g_invstd[DIM];
__device__ float g_cnorm[CODEBOOK_PAD];
__device__ int   g_idx[N_NODES];
__device__ float g_cacc[N_GRAPHS*DIM];
__device__ float g_sacc[N_GRAPHS*DIM];
__device__ float g_cmt[1];
__device__ __half g_cbs[(size_t)CODEBOOK_PAD * VQ_K];
__device__ float g_pd1[VQ_SEGS*NODE_PAD];
__device__ float g_pd2[VQ_SEGS*NODE_PAD];
__device__ int   g_pj1[VQ_SEGS*NODE_PAD];
__device__ int   g_flaglist[N_NODES];
__device__ int   g_flagcnt[1];
__device__ ull   g_best[N_NODES];

// ---------------- asm helpers ----------------
__device__ __forceinline__ uint32_t smem_u32(const void* p) {
    uint32_t a;
    asm("{ .reg .u64 t; cvta.to.shared.u64 t, %1; cvt.u32.u64 %0, t; }" : "=r"(a) : "l"(p));
    return a;
}
#define CP_ASYNC16(dst, src) \
    asm volatile("cp.async.cg.shared.global [%0], [%1], 16;" :: "r"(dst), "l"(src) : "memory")
#define CP_COMMIT() asm volatile("cp.async.commit_group;" ::: "memory")
#define CP_WAIT(n)  asm volatile("cp.async.wait_group %0;" :: "n"(n) : "memory")
#define LDSM4(r0,r1,r2,r3,addr) \
    asm volatile("ldmatrix.sync.aligned.m8n8.x4.shared.b16 {%0,%1,%2,%3}, [%4];" \
        : "=r"(r0), "=r"(r1), "=r"(r2), "=r"(r3) : "r"(addr))
#define MMA16816(d, a0,a1,a2,a3, b0,b1) \
    asm volatile("mma.sync.aligned.m16n8k16.row.col.f32.f16.f16.f32 " \
        "{%0,%1,%2,%3}, {%4,%5,%6,%7}, {%8,%9}, {%0,%1,%2,%3};" \
        : "+f"((d)[0]), "+f"((d)[1]), "+f"((d)[2]), "+f"((d)[3]) \
        : "r"(a0), "r"(a1), "r"(a2), "r"(a3), "r"(b0), "r"(b1))

__device__ __forceinline__ uint32_t fkey(float f) {
    uint32_t u = __float_as_uint(f);
    return (u & 0x80000000u) ? ~u : (u | 0x80000000u);
}
__device__ __forceinline__ void split16(float f, __half& hi, __half& lo) {
    hi = __float2half_rn(f);
    lo = __float2half_rn(f - __half2float(hi));
}

// ---------------- CSR build: edge-order deterministic ----------------------
__global__ void k_hist(const int* __restrict__ dst, int* __restrict__ deg) {
    int e = blockIdx.x * blockDim.x + threadIdx.x;
    if (e < N_EDGES) atomicAdd(&deg[dst[e]], 1);
}
__global__ void k_scan(const int* __restrict__ deg, int* __restrict__ offs) {
    __shared__ int sh[1024];
    __shared__ int carry;
    int tid = threadIdx.x;
    if (tid == 0) { carry = 0; offs[0] = 0; }
    __syncthreads();
    for (int base = 0; base < N_NODES; base += 1024) {
        int v = (base + tid < N_NODES) ? deg[base + tid] : 0;
        sh[tid] = v;
        __syncthreads();
        for (int o = 1; o < 1024; o <<= 1) {
            int t = (tid >= o) ? sh[tid - o] : 0;
            __syncthreads();
            sh[tid] += t;
            __syncthreads();
        }
        if (base + tid < N_NODES) offs[base + tid + 1] = carry + sh[tid];
        __syncthreads();
        if (tid == 0) carry += sh[1023];
        __syncthreads();
    }
}
__global__ void k_fill(const int* __restrict__ src, const int* __restrict__ dst,
                       int* __restrict__ cursor, ull* __restrict__ csrk) {
    int e = blockIdx.x * blockDim.x + threadIdx.x;
    if (e < N_EDGES) {
        int d = dst[e];
        int slot = atomicAdd(&cursor[d], 1);
        csrk[slot] = ((ull)(uint32_t)e << 32) | (uint32_t)src[e];
    }
}
__global__ void k_sortcsr(const int* __restrict__ offs, ull* __restrict__ csrk) {
    int n = blockIdx.x * blockDim.x + threadIdx.x;
    if (n >= N_NODES) return;
    int s = offs[n], e = offs[n + 1];
    for (int i = s + 1; i < e; i++) {
        ull v = csrk[i];
        int j = i - 1;
        while (j >= s && csrk[j] > v) { csrk[j + 1] = csrk[j]; j--; }
        csrk[j + 1] = v;
    }
}

// ---------------- aggregation: fp32, edge order (FROZEN) ------------------
__global__ void k_agg(const float* __restrict__ h, const int* __restrict__ offs,
                      const ull* __restrict__ csrk, float* __restrict__ z) {
    int warp = (blockIdx.x * blockDim.x + threadIdx.x) >> 5;
    int lane = threadIdx.x & 31;
    if (warp >= N_NODES) return;
    const float4* hv = (const float4*)h;
    float4 acc = hv[warp * 32 + lane];
    int s = offs[warp], e = offs[warp + 1];
    for (int i = s; i < e; i++) {
        int sidx = (int)(uint32_t)(__ldg(&csrk[i]) & 0xFFFFFFFFull);
        float4 v = hv[sidx * 32 + lane];
        acc.x += v.x; acc.y += v.y; acc.z += v.z; acc.w += v.w;
    }
    ((float4*)z)[warp * 32 + lane] = acc;
}

// ---------------- fused dual GEMM (FROZEN math): t2 = relu(relu(zW1+b1)W2+b2)
__global__ __launch_bounds__(256, 3) void k_gemm_fused(
        const float* __restrict__ A, const float* __restrict__ W1,
        const float* __restrict__ b1, const float* __restrict__ W2,
        const float* __restrict__ b2, float* __restrict__ out) {
    __shared__ float As[32][128];
    __shared__ float Ws[32][128];
    int tid = threadIdx.x;
    int tx = tid & 31, ty = tid >> 5;
    int row0 = blockIdx.x * 32;
    float acc[4][4];

#pragma unroll
    for (int it = 0; it < 4; it++) {
        int i = tid + it * 256;
        int r = i >> 5, c4 = i & 31;
        *(float4*)&As[r][c4 * 4] = *(const float4*)&A[(size_t)(row0 + r) * DIM + c4 * 4];
    }

#pragma unroll
    for (int r = 0; r < 4; r++)
#pragma unroll
        for (int c = 0; c < 4; c++) acc[r][c] = 0.f;
    for (int kt = 0; kt < DIM; kt += 32) {
#pragma unroll
        for (int it = 0; it < 4; it++) {
            int i = tid + it * 256;
            int r = i >> 5, c4 = i & 31;
            *(float4*)&Ws[r][c4 * 4] = *(const float4*)&W1[(size_t)(kt + r) * DIM + c4 * 4];
        }
        __syncthreads();
#pragma unroll
        for (int k = 0; k < 32; k++) {
            float4 w = *(float4*)&Ws[k][tx * 4];
#pragma unroll
            for (int r = 0; r < 4; r++) {
                float a = As[ty * 4 + r][kt + k];
                acc[r][0] += a * w.x;
                acc[r][1] += a * w.y;
                acc[r][2] += a * w.z;
                acc[r][3] += a * w.w;
            }
        }
        __syncthreads();
    }
    {
        float4 b = *(const float4*)&b1[tx * 4];
        __syncthreads();
#pragma unroll
        for (int r = 0; r < 4; r++) {
            float v0 = fmaxf(acc[r][0] + b.x, 0.f);
            float v1 = fmaxf(acc[r][1] + b.y, 0.f);
            float v2 = fmaxf(acc[r][2] + b.z, 0.f);
            float v3 = fmaxf(acc[r][3] + b.w, 0.f);
            *(float4*)&As[ty * 4 + r][tx * 4] = make_float4(v0, v1, v2, v3);
        }
        __syncthreads();
    }

#pragma unroll
    for (int r = 0; r < 4; r++)
#pragma unroll
        for (int c = 0; c < 4; c++) acc[r][c] = 0.f;
    for (int kt = 0; kt < DIM; kt += 32) {
#pragma unroll
        for (int it = 0; it < 4; it++) {
            int i = tid + it * 256;
            int r = i >> 5, c4 = i & 31;
            *(float4*)&Ws[r][c4 * 4] = *(const float4*)&W2[(size_t)(kt + r) * DIM + c4 * 4];
        }
        __syncthreads();
#pragma unroll
        for (int k = 0; k < 32; k++) {
            float4 w = *(float4*)&Ws[k][tx * 4];
#pragma unroll
            for (int r = 0; r < 4; r++) {
                float a = As[ty * 4 + r][kt + k];
                acc[r][0] += a * w.x;
                acc[r][1] += a * w.y;
                acc[r][2] += a * w.z;
                acc[r][3] += a * w.w;
            }
        }
        __syncthreads();
    }
    {
        float4 b = *(const float4*)&b2[tx * 4];
#pragma unroll
        for (int r = 0; r < 4; r++) {
            int row = row0 + ty * 4 + r;
            float v0 = fmaxf(acc[r][0] + b.x, 0.f);
            float v1 = fmaxf(acc[r][1] + b.y, 0.f);
            float v2 = fmaxf(acc[r][2] + b.z, 0.f);
            float v3 = fmaxf(acc[r][3] + b.w, 0.f);
            *(float4*)&out[(size_t)row * DIM + tx * 4] = make_float4(v0, v1, v2, v3);
        }
    }
}

// ---------------- head GEMM fp32 (FROZEN, small M) -------------------------
__global__ __launch_bounds__(256) void k_gemm(
        const float* __restrict__ A, const float* __restrict__ W,
        const float* __restrict__ bias, float* __restrict__ out,
        int M, int doRelu) {
    __shared__ float As[64][32];
    __shared__ float Ws[32][128];
    int tid = threadIdx.x;
    int tx = tid & 31, ty = tid >> 5;
    int row0 = blockIdx.x * 64;
    float acc[8][4];
#pragma unroll
    for (int r = 0; r < 8; r++)
#pragma unroll
        for (int c = 0; c < 4; c++) acc[r][c] = 0.f;

    for (int kt = 0; kt < DIM; kt += 32) {
#pragma unroll
        for (int it = 0; it < 2; it++) {
            int i = tid + it * 256;
            int r = i >> 3, c4 = i & 7;
            int row = row0 + r;
            float4 v = make_float4(0.f, 0.f, 0.f, 0.f);
            if (row < M) v = *(const float4*)&A[row * DIM + kt + c4 * 4];
            *(float4*)&As[r][c4 * 4] = v;
        }
#pragma unroll
        for (int it = 0; it < 4; it++) {
            int i = tid + it * 256;
            int r = i >> 5, c4 = i & 31;
            *(float4*)&Ws[r][c4 * 4] = *(const float4*)&W[(kt + r) * DIM + c4 * 4];
        }
        __syncthreads();
#pragma unroll
        for (int k = 0; k < 32; k++) {
            float4 w = *(float4*)&Ws[k][tx * 4];
#pragma unroll
            for (int r = 0; r < 8; r++) {
                float a = As[ty * 8 + r][k];
                acc[r][0] += a * w.x;
                acc[r][1] += a * w.y;
                acc[r][2] += a * w.z;
                acc[r][3] += a * w.w;
            }
        }
        __syncthreads();
    }
    float4 b = *(const float4*)&bias[tx * 4];
#pragma unroll
    for (int r = 0; r < 8; r++) {
        int row = row0 + ty * 8 + r;
        if (row < M) {
            float v0 = acc[r][0] + b.x;
            float v1 = acc[r][1] + b.y;
            float v2 = acc[r][2] + b.z;
            float v3 = acc[r][3] + b.w;
            if (doRelu) {
                v0 = fmaxf(v0, 0.f); v1 = fmaxf(v1, 0.f);
                v2 = fmaxf(v2, 0.f); v3 = fmaxf(v3, 0.f);
            }
            *(float4*)&out[row * DIM + tx * 4] = make_float4(v0, v1, v2, v3);
        }
    }
}

// ---------------- BN stats (FROZEN) ---------------------------------------
__global__ void k_stats(const float* __restrict__ t2, float* __restrict__ pstats) {
    __shared__ float ss[256], qq[256];
    int tid = threadIdx.x;
    int col = tid & 127, half = tid >> 7;
    float s = 0.f, q = 0.f;
    int row0 = blockIdx.x * 128;
    for (int i = half; i < 128; i += 2) {
        int r = row0 + i;
        if (r < N_NODES) {
            float v = t2[(size_t)r * DIM + col];
            s += v; q += v * v;
        }
    }
    ss[tid] = s; qq[tid] = q;
    __syncthreads();
    if (tid < 128) {
        pstats[blockIdx.x * 256 + tid]       = ss[tid] + ss[tid + 128];
        pstats[blockIdx.x * 256 + 128 + tid] = qq[tid] + qq[tid + 128];
    }
}

__global__ void k_bnfin(const float* __restrict__ pstats,
                        float* __restrict__ mean, float* __restrict__ invstd) {
    int d = threadIdx.x;
    float s = 0.f, q = 0.f;
    for (int b = 0; b < STAT_BLOCKS; b++) {
        s += pstats[b * 256 + d];
        q += pstats[b * 256 + 128 + d];
    }
    float mu = s / (float)N_NODES;
    float var = q / (float)N_NODES - mu * mu;
    mean[d] = mu;
    invstd[d] = rsqrtf(var + BN_EPS);
}

__global__ void k_bnapply(const float* __restrict__ z, const float* __restrict__ mean,
                          const float* __restrict__ invstd, const float* __restrict__ gamma,
                          const float* __restrict__ beta, float* __restrict__ h) {
    int i = blockIdx.x * blockDim.x + threadIdx.x;
    if (i < N_NODES * DIM) {
        int d = i & (DIM - 1);
        h[i] = (z[i] - mean[d]) * invstd[d] * gamma[d] + beta[d];
    }
}

// ---------------- codebook prep: norms + fp16 split, one pass -------------
__global__ void k_cbprep(const float* __restrict__ cb, float* __restrict__ cnorm,
                         __half* __restrict__ cbs) {
    int warp = (blockIdx.x * blockDim.x + threadIdx.x) >> 5;
    int lane = threadIdx.x & 31;
    if (warp >= CODEBOOK_PAD) return;
    __half* row = cbs + (size_t)warp * VQ_K;
    if (warp >= CODEBOOK_N) {
        if (lane == 0) cnorm[warp] = 1e30f;
        *(ull*)&row[lane * 4] = 0ull;
        *(ull*)&row[128 + lane * 4] = 0ull;
        return;
    }
    float4 v = ((const float4*)cb)[warp * 32 + lane];
    __half hx, lx, hy, ly, hz, lz, hw, lw;
    split16(v.x, hx, lx); split16(v.y, hy, ly);
    split16(v.z, hz, lz); split16(v.w, hw, lw);
    row[lane * 4 + 0] = hx; row[lane * 4 + 1] = hy;
    row[lane * 4 + 2] = hz; row[lane * 4 + 3] = hw;
    row[128 + lane * 4 + 0] = lx; row[128 + lane * 4 + 1] = ly;
    row[128 + lane * 4 + 2] = lz; row[128 + lane * 4 + 3] = lw;
    float s = v.x * v.x + v.y * v.y + v.z * v.z + v.w * v.w;
#pragma unroll
    for (int o = 16; o; o >>= 1) s += __shfl_xor_sync(0xffffffffu, s, o);
    if (lane == 0) cnorm[warp] = s;
}

// ---------------- VQ main: segment-split fp16 3-term GEMM-argmin -----------
__global__ __launch_bounds__(256, 2) void k_vq_mma(
        const float* __restrict__ h, const __half* __restrict__ cbs,
        const float* __restrict__ cnorm,
        float* __restrict__ pd1, float* __restrict__ pd2, int* __restrict__ pj1) {
    extern __shared__ __align__(16) char dyn[];
    __half* As = (__half*)dyn;                 // [64][264]
    __half* Bs = As + 64 * AS_STRIDE;          // [4][64][72]
    float* cns = (float*)(Bs + 4 * BS_BUF_H);  // [64]
    float* rD1 = cns + 64;                     // [64][4]
    float* rD2 = rD1 + 256;
    int*   rJ1 = (int*)(rD2 + 256);
    uint32_t As_u = smem_u32(As);
    uint32_t Bs_u = smem_u32(Bs);

    int tid = threadIdx.x, lane = tid & 31, wid = tid >> 5;
    int warp_m = wid & 1, warp_n = wid >> 1;   // 2m x 4n
    int node0 = blockIdx.x * 64;
    int seg = blockIdx.y;
    int cstart = seg * VQ_CPS;
    int cend = cstart + VQ_CPS;

    {
        int r = tid >> 2, q = tid & 3;
        bool valid = (node0 + r) < N_NODES;
        const float4* hp = (const float4*)(h + (size_t)(valid ? node0 + r : 0) * DIM);
        __half* arow = As + r * AS_STRIDE;
#pragma unroll
        for (int v = 0; v < 8; v++) {
            float4 f = valid ? hp[q * 8 + v] : make_float4(0.f, 0.f, 0.f, 0.f);
            __half hx, lx, hy, ly, hz, lz, hw, lw;
            split16(f.x, hx, lx); split16(f.y, hy, ly);
            split16(f.z, hz, lz); split16(f.w, hw, lw);
            int col = q * 32 + v * 4;
            arow[col + 0] = hx; arow[col + 1] = hy; arow[col + 2] = hz; arow[col + 3] = hw;
            arow[128 + col + 0] = lx; arow[128 + col + 1] = ly;
            arow[128 + col + 2] = lz; arow[128 + col + 3] = lw;
        }
    }

#pragma unroll
    for (int pc = 0; pc < 2; pc++) {
        int ci = cstart + pc;
        const __half* base = cbs + (size_t)(ci >> 2) * 64 * VQ_K + (ci & 3) * 64;
#pragma unroll
        for (int it = 0; it < 2; it++) {
            int i = tid + it * 256;
            int row = i >> 3, c16 = i & 7;
            CP_ASYNC16(Bs_u + (uint32_t)(pc * BS_BUF_H + row * BS_STRIDE + c16 * 8) * 2,
                       base + (size_t)row * VQ_K + c16 * 8);
        }
        CP_COMMIT();
    }

    float d1v[2][2] = {{1e38f, 1e38f}, {1e38f, 1e38f}};
    float d2v[2][2] = {{1e38f, 1e38f}, {1e38f, 1e38f}};
    int   j1v[2][2] = {{0, 0}, {0, 0}};
    int lr = lane & 7, g = lane >> 3;
    float acc[2][2][4];

    for (int ci = cstart; ci < cend; ci++) {
        int t = ci >> 2, c = ci & 3;
        int buf = ci & 3;
        if (c == 0) {
#pragma unroll
            for (int mt = 0; mt < 2; mt++)
#pragma unroll
                for (int hf = 0; hf < 2; hf++)
#pragma unroll
                    for (int r = 0; r < 4; r++) acc[mt][hf][r] = 0.f;
        }
        if (ci + 2 < cend) {
            int pidx = ci + 2;
            int pbuf = pidx & 3;
            const __half* base = cbs + (size_t)(pidx >> 2) * 64 * VQ_K + (pidx & 3) * 64;
#pragma unroll
            for (int it = 0; it < 2; it++) {
                int i = tid + it * 256;
                int row = i >> 3, c16 = i & 7;
                CP_ASYNC16(Bs_u + (uint32_t)(pbuf * BS_BUF_H + row * BS_STRIDE + c16 * 8) * 2,
                           base + (size_t)row * VQ_K + c16 * 8);
            }
            CP_COMMIT();
            CP_WAIT(2);
        } else {
            CP_WAIT(0);
        }
        __syncthreads();
        if (c == 0 && tid < 64) cns[tid] = __ldg(&cnorm[t * 64 + tid]);

        uint32_t bbase = Bs_u + (uint32_t)(buf * BS_BUF_H) * 2;
        if (c < 2) {
#pragma unroll
            for (int kk = 0; kk < 4; kk++) {
                int kcol = c * 64 + kk * 16;
                uint32_t ah0[2], ah1[2], ah2[2], ah3[2];
                uint32_t al0[2], al1[2], al2[2], al3[2];
#pragma unroll
                for (int mt = 0; mt < 2; mt++) {
                    uint32_t abase = As_u +
                        (uint32_t)((warp_m * 32 + mt * 16 + lr + ((g & 1) << 3)) * AS_STRIDE
                                   + kcol + ((g >> 1) << 3)) * 2;
                    LDSM4(ah0[mt], ah1[mt], ah2[mt], ah3[mt], abase);
                    LDSM4(al0[mt], al1[mt], al2[mt], al3[mt], abase + 128 * 2);
                }
                uint32_t b0, b1, b2, b3;
                uint32_t baddr = bbase +
                    (uint32_t)((warp_n * 16 + lr + ((g >> 1) << 3)) * BS_STRIDE
                               + kk * 16 + ((g & 1) << 3)) * 2;
                LDSM4(b0, b1, b2, b3, baddr);
#pragma unroll
                for (int mt = 0; mt < 2; mt++) {
                    MMA16816(acc[mt][0], ah0[mt], ah1[mt], ah2[mt], ah3[mt], b0, b1);
                    MMA16816(acc[mt][1], ah0[mt], ah1[mt], ah2[mt], ah3[mt], b2, b3);
                    MMA16816(acc[mt][0], al0[mt], al1[mt], al2[mt], al3[mt], b0, b1);
                    MMA16816(acc[mt][1], al0[mt], al1[mt], al2[mt], al3[mt], b2, b3);
                }
            }
        } else {
            int cc = c - 2;
#pragma unroll
            for (int kk = 0; kk < 4; kk++) {
                int kcol = cc * 64 + kk * 16;
                uint32_t ah0[2], ah1[2], ah2[2], ah3[2];
#pragma unroll
                for (int mt = 0; mt < 2; mt++) {
                    uint32_t abase = As_u +
                        (uint32_t)((warp_m * 32 + mt * 16 + lr + ((g & 1) << 3)) * AS_STRIDE
                                   + kcol + ((g >> 1) << 3)) * 2;
                    LDSM4(ah0[mt], ah1[mt], ah2[mt], ah3[mt], abase);
                }
                uint32_t b0, b1, b2, b3;
                uint32_t baddr = bbase +
                    (uint32_t)((warp_n * 16 + lr + ((g >> 1) << 3)) * BS_STRIDE
                               + kk * 16 + ((g & 1) << 3)) * 2;
                LDSM4(b0, b1, b2, b3, baddr);
#pragma unroll
                for (int mt = 0; mt < 2; mt++) {
                    MMA16816(acc[mt][0], ah0[mt], ah1[mt], ah2[mt], ah3[mt], b0, b1);
                    MMA16816(acc[mt][1], ah0[mt], ah1[mt], ah2[mt], ah3[mt], b2, b3);
                }
            }
        }

        if (c == VQ_CPT - 1) {
            int cb0 = warp_n * 16;
            int lcol = 2 * (lane & 3);
#pragma unroll
            for (int hf = 0; hf < 2; hf++) {
                int cloc = cb0 + hf * 8 + lcol;
                float cn0 = cns[cloc], cn1 = cns[cloc + 1];
                int code = t * 64 + cloc;
#pragma unroll
                for (int mt = 0; mt < 2; mt++)
#pragma unroll
                    for (int rs = 0; rs < 2; rs++) {
                        float dA = cn0 - 2.f * acc[mt][hf][rs * 2 + 0];
                        float dB = cn1 - 2.f * acc[mt][hf][rs * 2 + 1];
                        if (dA < d1v[mt][rs]) { d2v[mt][rs] = d1v[mt][rs]; d1v[mt][rs] = dA; j1v[mt][rs] = code; }
                        else if (dA < d2v[mt][rs]) d2v[mt][rs] = dA;
                        if (dB < d1v[mt][rs]) { d2v[mt][rs] = d1v[mt][rs]; d1v[mt][rs] = dB; j1v[mt][rs] = code + 1; }
                        else if (dB < d2v[mt][rs]) d2v[mt][rs] = dB;
                    }
            }
        }
    }

#pragma unroll
    for (int o = 1; o <= 2; o <<= 1) {
#pragma unroll
        for (int mt = 0; mt < 2; mt++)
#pragma unroll
            for (int rs = 0; rs < 2; rs++) {
                float od1 = __shfl_xor_sync(0xffffffffu, d1v[mt][rs], o);
                float od2 = __shfl_xor_sync(0xffffffffu, d2v[mt][rs], o);
                int   oj  = __shfl_xor_sync(0xffffffffu, j1v[mt][rs], o);
                if (od1 < d1v[mt][rs] || (od1 == d1v[mt][rs] && oj < j1v[mt][rs])) {
                    d2v[mt][rs] = fminf(d1v[mt][rs], od2);
                    d1v[mt][rs] = od1; j1v[mt][rs] = oj;
                } else {
                    d2v[mt][rs] = fminf(d2v[mt][rs], od1);
                }
            }
    }
    __syncthreads();
    if ((lane & 3) == 0) {
#pragma unroll
        for (int mt = 0; mt < 2; mt++)
#pragma unroll
            for (int rs = 0; rs < 2; rs++) {
                int nl = warp_m * 32 + mt * 16 + rs * 8 + (lane >> 2);
                rD1[nl * 4 + warp_n] = d1v[mt][rs];
                rD2[nl * 4 + warp_n] = d2v[mt][rs];
                rJ1[nl * 4 + warp_n] = j1v[mt][rs];
            }
    }
    __syncthreads();
    if (tid < 64) {
        float f1 = rD1[tid * 4], f2 = rD2[tid * 4];
        int fj = rJ1[tid * 4];
#pragma unroll
        for (int wn = 1; wn < 4; wn++) {
            float b1 = rD1[tid * 4 + wn], b2 = rD2[tid * 4 + wn];
            int bj = rJ1[tid * 4 + wn];
            if (b1 < f1 || (b1 == f1 && bj < fj)) {
                f2 = fminf(f1, b2); f1 = b1; fj = bj;
            } else {
                f2 = fminf(f2, b1);
            }
        }
        int slot = seg * NODE_PAD + node0 + tid;
        pd1[slot] = f1; pd2[slot] = f2; pj1[slot] = fj;
    }
}

// ---------------- merge segments (deterministic, fixed order) --------------
__global__ void k_vqmerge(const float* __restrict__ pd1, const float* __restrict__ pd2,
                          const int* __restrict__ pj1, int* __restrict__ outidx,
                          int* __restrict__ flaglist, int* __restrict__ flagcnt) {
    int n = blockIdx.x * blockDim.x + threadIdx.x;
    if (n >= N_NODES) return;
    float f1 = pd1[n], f2 = pd2[n];
    int fj = pj1[n];
#pragma unroll
    for (int s = 1; s < VQ_SEGS; s++) {
        float b1 = pd1[s * NODE_PAD + n], b2 = pd2[s * NODE_PAD + n];
        int bj = pj1[s * NODE_PAD + n];
        if (b1 < f1 || (b1 == f1 && bj < fj)) {
            f2 = fminf(f1, b2); f1 = b1; fj = bj;
        } else {
            f2 = fminf(f2, b1);
        }
    }
    outidx[n] = fj;
    if (f2 - f1 < VQ_MARGIN) {
        int p = atomicAdd(flagcnt, 1);
        flaglist[p] = n;
    }
}

// ---------------- exact fp32 rescue (order-invariant via atomicMin) --------
__global__ __launch_bounds__(128) void k_rescue(
        const float* __restrict__ h, const float* __restrict__ cb,
        const float* __restrict__ cnorm, const int* __restrict__ flaglist,
        const int* __restrict__ flagcnt, ull* __restrict__ best) {
    extern __shared__ __align__(16) float rs[];
    float* cs   = rs;
    float* hrow = cs + 128 * 128;
    float* rd   = hrow + 128;
    int*   rj   = (int*)(rd + 128);
    int tid = threadIdx.x;
    int c0 = blockIdx.x * 128;
    int code = c0 + tid;
#pragma unroll
    for (int it = 0; it < 32; it++) {
        int i = tid + it * 128;
        int row = i >> 5, c4 = i & 31;
        float4 v = make_float4(0.f, 0.f, 0.f, 0.f);
        if (c0 + row < CODEBOOK_N) v = __ldg(&((const float4*)cb)[(size_t)(c0 + row) * 32 + c4]);
        *(float4*)&cs[row * 128 + c4 * 4] = v;
    }
    float cn = cnorm[code];
    __syncthreads();
    int cnt = *flagcnt;
    const float4* crow4 = (const float4*)&cs[tid * 128];
    const float4* h4 = (const float4*)hrow;
    for (int f = 0; f < cnt; f++) {
        int node = flaglist[f];
        if (tid < 32) ((float4*)hrow)[tid] = ((const float4*)(h + (size_t)node * DIM))[tid];
        __syncthreads();
        float dot = 0.f;
#pragma unroll
        for (int k4 = 0; k4 < 32; k4++) {
            int i = (k4 + tid) & 31;
            float4 cv = crow4[i];
            float4 hv = h4[i];
            dot += cv.x * hv.x + cv.y * hv.y + cv.z * hv.z + cv.w * hv.w;
        }
        float d = cn - 2.f * dot;
        rd[tid] = d; rj[tid] = code;
        __syncthreads();
        for (int o = 64; o; o >>= 1) {
            if (tid < o) {
                float od = rd[tid + o]; int oc = rj[tid + o];
                if (od < rd[tid] || (od == rd[tid] && oc < rj[tid])) {
                    rd[tid] = od; rj[tid] = oc;
                }
            }
            __syncthreads();
        }
        if (tid == 0) {
            ull key = ((ull)fkey(rd[0]) << 32) | (uint32_t)rj[0];
            atomicMin(&best[node], key);
        }
        __syncthreads();
    }
}

__global__ void k_flagapply(const int* __restrict__ flaglist, const int* __restrict__ flagcnt,
                            const ull* __restrict__ best, int* __restrict__ outidx) {
    int cnt = *flagcnt;
    for (int i = blockIdx.x * blockDim.x + threadIdx.x; i < cnt; i += gridDim.x * blockDim.x) {
        int node = flaglist[i];
        outidx[node] = (int)(best[node] & 0xFFFFFFFFull);
    }
}

// ---------------- final per-node ----------------
__global__ void k_final(const float* __restrict__ h, const float* __restrict__ cb,
                        const int* __restrict__ idx, const float* __restrict__ score,
                        const int* __restrict__ batch, float* __restrict__ cacc,
                        float* __restrict__ sacc, float* __restrict__ cmt) {
    __shared__ float sh[256];
    int i = blockIdx.x * blockDim.x + threadIdx.x;
    float local = 0.f;
    if (i < N_NODES * DIM) {
        int node = i >> 7, d = i & 127;
        float hv = h[i];
        float q = cb[idx[node] * DIM + d];
        float diff = q - hv;
        local = diff * diff;
        float res = hv + q;
        float sc = score[node];
        int b = batch[node];
        atomicAdd(&cacc[b * DIM + d], res * sc);
        atomicAdd(&sacc[b * DIM + d], res * (1.f - sc));
    }
    sh[threadIdx.x] = local;
    __syncthreads();
    for (int o = 128; o; o >>= 1) {
        if (threadIdx.x < o) sh[threadIdx.x] += sh[threadIdx.x + o];
        __syncthreads();
    }
    if (threadIdx.x == 0) atomicAdd(cmt, sh[0]);
}

__global__ void k_cmtfin(const float* __restrict__ cmt, float* __restrict__ out) {
    out[2 * N_GRAPHS * DIM] = COMMIT_W * cmt[0] / (float)(N_NODES * DIM);
}

// ---------------- launcher ----------------
extern "C" void kernel_launch(void* const* d_in, const int* in_sizes, int n_in,
                              void* d_out, int out_size) {
    const float* x        = (const float*)d_in[0];
    const int*   ei       = (const int*)  d_in[1];
    const int*   batch    = (const int*)  d_in[2];
    const float* score    = (const float*)d_in[3];
    const float* cW1      = (const float*)d_in[4];
    const float* cb1      = (const float*)d_in[5];
    const float* cW2      = (const float*)d_in[6];
    const float* cb2      = (const float*)d_in[7];
    const float* bng      = (const float*)d_in[8];
    const float* bnb      = (const float*)d_in[9];
    const float* codebook = (const float*)d_in[10];
    const float* fc1W     = (const float*)d_in[11];
    const float* fc1b     = (const float*)d_in[12];
    const float* fc2W     = (const float*)d_in[13];
    const float* fc2b     = (const float*)d_in[14];
    float* out = (float*)d_out;
    const int* src = ei;
    const int* dst = ei + N_EDGES;

    void *p_z, *p_t2, *p_h, *p_deg, *p_offs, *p_cursor, *p_csrk;
    void *p_pstats, *p_mean, *p_invstd, *p_cnorm, *p_idx, *p_cacc, *p_sacc, *p_cmt;
    void *p_cbs, *p_pd1, *p_pd2, *p_pj1, *p_flag, *p_fcnt, *p_best;
    cudaGetSymbolAddress(&p_z, g_z);
    cudaGetSymbolAddress(&p_t2, g_t2);
    cudaGetSymbolAddress(&p_h, g_h);
    cudaGetSymbolAddress(&p_deg, g_deg);
    cudaGetSymbolAddress(&p_offs, g_offs);
    cudaGetSymbolAddress(&p_cursor, g_cursor);
    cudaGetSymbolAddress(&p_csrk, g_csrk);
    cudaGetSymbolAddress(&p_pstats, g_pstats);
    cudaGetSymbolAddress(&p_mean, g_mean);
    cudaGetSymbolAddress(&p_invstd, g_invstd);
    cudaGetSymbolAddress(&p_cnorm, g_cnorm);
    cudaGetSymbolAddress(&p_idx, g_idx);
    cudaGetSymbolAddress(&p_cacc, g_cacc);
    cudaGetSymbolAddress(&p_sacc, g_sacc);
    cudaGetSymbolAddress(&p_cmt, g_cmt);
    cudaGetSymbolAddress(&p_cbs, g_cbs);
    cudaGetSymbolAddress(&p_pd1, g_pd1);
    cudaGetSymbolAddress(&p_pd2, g_pd2);
    cudaGetSymbolAddress(&p_pj1, g_pj1);
    cudaGetSymbolAddress(&p_flag, g_flaglist);
    cudaGetSymbolAddress(&p_fcnt, g_flagcnt);
    cudaGetSymbolAddress(&p_best, g_best);

    const int SMEM_VQ = 64 * AS_STRIDE * 2 + 4 * BS_BUF_H * 2 + 64 * 4 + 256 * 4 * 3;
    const int SMEM_RESCUE = 128 * 128 * 4 + 128 * 4 * 3;
    static bool attr_set = false;
    if (!attr_set) {
        cudaFuncSetAttribute(k_vq_mma, cudaFuncAttributeMaxDynamicSharedMemorySize, SMEM_VQ);
        cudaFuncSetAttribute(k_rescue, cudaFuncAttributeMaxDynamicSharedMemorySize, SMEM_RESCUE);
        attr_set = true;
    }

    // CSR build, canonicalized to exact EDGE order (FROZEN)
    cudaMemsetAsync(p_deg, 0, N_NODES * sizeof(int));
    k_hist<<<(N_EDGES + 255) / 256, 256>>>(dst, (int*)p_deg);
    k_scan<<<1, 1024>>>((const int*)p_deg, (int*)p_offs);
    cudaMemcpyAsync(p_cursor, p_offs, N_NODES * sizeof(int), cudaMemcpyDeviceToDevice);
    k_fill<<<(N_EDGES + 255) / 256, 256>>>(src, dst, (int*)p_cursor, (ull*)p_csrk);
    k_sortcsr<<<(N_NODES + 127) / 128, 128>>>((const int*)p_offs, (ull*)p_csrk);

    // codebook prep (one pass: norm + fp16 split)
    k_cbprep<<<(CODEBOOK_PAD * 32 + 255) / 256, 256>>>(codebook, (float*)p_cnorm,
                                                       (__half*)p_cbs);

    // MLP chain: R14-proven structure (h bitwise identical)
    const float* h = x;
    for (int l = 0; l < N_LAYERS; l++) {
        k_agg<<<(N_NODES * 32 + 255) / 256, 256>>>(h, (const int*)p_offs,
                                                   (const ull*)p_csrk, (float*)p_z);
        k_gemm_fused<<<N_NODES / 32, 256>>>(
            (const float*)p_z, cW1 + l * DIM * DIM, cb1 + l * DIM,
            cW2 + l * DIM * DIM, cb2 + l * DIM, (float*)p_t2);
        k_stats<<<STAT_BLOCKS, 256>>>((const float*)p_t2, (float*)p_pstats);
        k_bnfin<<<1, 128>>>((const float*)p_pstats, (float*)p_mean, (float*)p_invstd);
        k_bnapply<<<(N_NODES * DIM + 255) / 256, 256>>>(
            (const float*)p_t2, (const float*)p_mean, (const float*)p_invstd,
            bng + l * DIM, bnb + l * DIM, (float*)p_h);
        h = (const float*)p_h;
    }

    // VQ: segment-split tensor-core search + deterministic merge + exact rescue
    cudaMemsetAsync(p_fcnt, 0, sizeof(int));
    cudaMemsetAsync(p_best, 0xFF, N_NODES * sizeof(ull));
    k_vq_mma<<<dim3(VQ_MBLK, VQ_SEGS), 256, SMEM_VQ>>>(
        (const float*)p_h, (const __half*)p_cbs, (const float*)p_cnorm,
        (float*)p_pd1, (float*)p_pd2, (int*)p_pj1);
    k_vqmerge<<<(N_NODES + 255) / 256, 256>>>(
        (const float*)p_pd1, (const float*)p_pd2, (const int*)p_pj1,
        (int*)p_idx, (int*)p_flag, (int*)p_fcnt);
    k_rescue<<<CODEBOOK_PAD / 128, 128, SMEM_RESCUE>>>(
        (const float*)p_h, codebook, (const float*)p_cnorm,
        (const int*)p_flag, (const int*)p_fcnt, (ull*)p_best);
    k_flagapply<<<40, 256>>>((const int*)p_flag, (const int*)p_fcnt,
                             (const ull*)p_best, (int*)p_idx);

    cudaMemsetAsync(p_cacc, 0, N_GRAPHS * DIM * sizeof(float));
    cudaMemsetAsync(p_sacc, 0, N_GRAPHS * DIM * sizeof(float));
    cudaMemsetAsync(p_cmt, 0, sizeof(float));
    k_final<<<(N_NODES * DIM + 255) / 256, 256>>>(
        (const float*)p_h, codebook, (const int*)p_idx, score, batch,
        (float*)p_cacc, (float*)p_sacc, (float*)p_cmt);

    k_gemm<<<(N_GRAPHS + 63) / 64, 256>>>((const float*)p_cacc, fc1W, fc1b,
                                          out, N_GRAPHS, 1);
    k_gemm<<<(N_GRAPHS + 63) / 64, 256>>>((const float*)p_sacc, fc2W, fc2b,
                                          out + N_GRAPHS * DIM, N_GRAPHS, 1);
    k_cmtfin<<<1, 1>>>((const float*)p_cmt, out);
}

// round 17
// speedup vs baseline: 1.5248x; 1.0140x over previous
#include <cuda_runtime.h>
#include <cuda_fp16.h>
#include <cstdint>
#include <math.h>

#define N_NODES   20000
#define N_EDGES   320000
#define DIM       128
#define CODEBOOK_N 12000
#define CODEBOOK_PAD 12032
#define N_GRAPHS  256
#define N_LAYERS  5
#define BN_EPS    1e-5f
#define COMMIT_W  0.25f
#define STAT_BLOCKS 157
#define NODE_PAD  20032            // 313*64

// VQ: exact fp16 3-term product via pass pairing, 4-way codebook split.
#define VQ_K       256
#define VQ_TILES   188
#define VQ_CPT     4
#define VQ_SEGS    4
#define VQ_TPS     47
#define VQ_CPS     (VQ_TPS*VQ_CPT)
#define VQ_MBLK    313
#define VQ_MARGIN  0.02f
#define AS_STRIDE  264
#define BS_STRIDE  72
#define BS_BUF_H   (64*BS_STRIDE)

typedef unsigned long long ull;

// ---------------- scratch ----------------
__device__ float g_z [N_NODES*DIM];
__device__ float g_t2[N_NODES*DIM];
__device__ float g_h [N_NODES*DIM];
__device__ int   g_deg[N_NODES];
__device__ int   g_offs[N_NODES+1];
__device__ int   g_cursor[N_NODES];
__device__ ull   g_csrk[N_EDGES];   // (edge_idx<<32)|src — sorted per node = edge order
__device__ float g_pstats[STAT_BLOCKS*2*DIM];
__device__ float g_mean[DIM];
__device__ float g_invstd[DIM];
__device__ float g_cnorm[CODEBOOK_PAD];
__device__ int   g_idx[N_NODES];
__device__ float g_cacc[N_GRAPHS*DIM];
__device__ float g_sacc[N_GRAPHS*DIM];
__device__ float g_cmt[1];
__device__ __half g_cbs[(size_t)CODEBOOK_PAD * VQ_K];
__device__ float g_pd1[VQ_SEGS*NODE_PAD];
__device__ float g_pd2[VQ_SEGS*NODE_PAD];
__device__ int   g_pj1[VQ_SEGS*NODE_PAD];
__device__ int   g_flaglist[N_NODES];
__device__ int   g_flagcnt[1];
__device__ ull   g_best[N_NODES];

// ---------------- asm helpers ----------------
__device__ __forceinline__ uint32_t smem_u32(const void* p) {
    uint32_t a;
    asm("{ .reg .u64 t; cvta.to.shared.u64 t, %1; cvt.u32.u64 %0, t; }" : "=r"(a) : "l"(p));
    return a;
}
#define CP_ASYNC16(dst, src) \
    asm volatile("cp.async.cg.shared.global [%0], [%1], 16;" :: "r"(dst), "l"(src) : "memory")
#define CP_COMMIT() asm volatile("cp.async.commit_group;" ::: "memory")
#define CP_WAIT(n)  asm volatile("cp.async.wait_group %0;" :: "n"(n) : "memory")
#define LDSM4(r0,r1,r2,r3,addr) \
    asm volatile("ldmatrix.sync.aligned.m8n8.x4.shared.b16 {%0,%1,%2,%3}, [%4];" \
        : "=r"(r0), "=r"(r1), "=r"(r2), "=r"(r3) : "r"(addr))
#define MMA16816(d, a0,a1,a2,a3, b0,b1) \
    asm volatile("mma.sync.aligned.m16n8k16.row.col.f32.f16.f16.f32 " \
        "{%0,%1,%2,%3}, {%4,%5,%6,%7}, {%8,%9}, {%0,%1,%2,%3};" \
        : "+f"((d)[0]), "+f"((d)[1]), "+f"((d)[2]), "+f"((d)[3]) \
        : "r"(a0), "r"(a1), "r"(a2), "r"(a3), "r"(b0), "r"(b1))

__device__ __forceinline__ uint32_t fkey(float f) {
    uint32_t u = __float_as_uint(f);
    return (u & 0x80000000u) ? ~u : (u | 0x80000000u);
}
__device__ __forceinline__ void split16(float f, __half& hi, __half& lo) {
    hi = __float2half_rn(f);
    lo = __float2half_rn(f - __half2float(hi));
}

// ---------------- CSR build: edge-order deterministic ----------------------
__global__ void k_hist(const int* __restrict__ dst, int* __restrict__ deg) {
    int e = blockIdx.x * blockDim.x + threadIdx.x;
    if (e < N_EDGES) atomicAdd(&deg[dst[e]], 1);
}
__global__ void k_scan(const int* __restrict__ deg, int* __restrict__ offs) {
    __shared__ int sh[1024];
    __shared__ int carry;
    int tid = threadIdx.x;
    if (tid == 0) { carry = 0; offs[0] = 0; }
    __syncthreads();
    for (int base = 0; base < N_NODES; base += 1024) {
        int v = (base + tid < N_NODES) ? deg[base + tid] : 0;
        sh[tid] = v;
        __syncthreads();
        for (int o = 1; o < 1024; o <<= 1) {
            int t = (tid >= o) ? sh[tid - o] : 0;
            __syncthreads();
            sh[tid] += t;
            __syncthreads();
        }
        if (base + tid < N_NODES) offs[base + tid + 1] = carry + sh[tid];
        __syncthreads();
        if (tid == 0) carry += sh[1023];
        __syncthreads();
    }
}
__global__ void k_fill(const int* __restrict__ src, const int* __restrict__ dst,
                       int* __restrict__ cursor, ull* __restrict__ csrk) {
    int e = blockIdx.x * blockDim.x + threadIdx.x;
    if (e < N_EDGES) {
        int d = dst[e];
        int slot = atomicAdd(&cursor[d], 1);
        csrk[slot] = ((ull)(uint32_t)e << 32) | (uint32_t)src[e];
    }
}
__global__ void k_sortcsr(const int* __restrict__ offs, ull* __restrict__ csrk) {
    int n = blockIdx.x * blockDim.x + threadIdx.x;
    if (n >= N_NODES) return;
    int s = offs[n], e = offs[n + 1];
    for (int i = s + 1; i < e; i++) {
        ull v = csrk[i];
        int j = i - 1;
        while (j >= s && csrk[j] > v) { csrk[j + 1] = csrk[j]; j--; }
        csrk[j + 1] = v;
    }
}

// ---------------- aggregation: fp32, edge order (FROZEN math) -------------
// prefetch next index one iteration ahead; FADD sequence on acc unchanged.
__global__ void k_agg(const float* __restrict__ h, const int* __restrict__ offs,
                      const ull* __restrict__ csrk, float* __restrict__ z) {
    int warp = (blockIdx.x * blockDim.x + threadIdx.x) >> 5;
    int lane = threadIdx.x & 31;
    if (warp >= N_NODES) return;
    const float4* hv = (const float4*)h;
    float4 acc = hv[warp * 32 + lane];
    int s = offs[warp], e = offs[warp + 1];
    if (s < e) {
        int sidx = (int)(uint32_t)(__ldg(&csrk[s]) & 0xFFFFFFFFull);
        for (int i = s; i < e; i++) {
            int nidx = (i + 1 < e) ? (int)(uint32_t)(__ldg(&csrk[i + 1]) & 0xFFFFFFFFull) : 0;
            float4 v = hv[sidx * 32 + lane];
            acc.x += v.x; acc.y += v.y; acc.z += v.z; acc.w += v.w;
            sidx = nidx;
        }
    }
    ((float4*)z)[warp * 32 + lane] = acc;
}

// ---------------- fused dual GEMM (FROZEN math), occ 4 --------------------
__global__ __launch_bounds__(256, 4) void k_gemm_fused(
        const float* __restrict__ A, const float* __restrict__ W1,
        const float* __restrict__ b1, const float* __restrict__ W2,
        const float* __restrict__ b2, float* __restrict__ out) {
    __shared__ float As[32][128];
    __shared__ float Ws[32][128];
    int tid = threadIdx.x;
    int tx = tid & 31, ty = tid >> 5;
    int row0 = blockIdx.x * 32;
    float acc[4][4];

#pragma unroll
    for (int it = 0; it < 4; it++) {
        int i = tid + it * 256;
        int r = i >> 5, c4 = i & 31;
        *(float4*)&As[r][c4 * 4] = *(const float4*)&A[(size_t)(row0 + r) * DIM + c4 * 4];
    }

#pragma unroll
    for (int r = 0; r < 4; r++)
#pragma unroll
        for (int c = 0; c < 4; c++) acc[r][c] = 0.f;
    for (int kt = 0; kt < DIM; kt += 32) {
#pragma unroll
        for (int it = 0; it < 4; it++) {
            int i = tid + it * 256;
            int r = i >> 5, c4 = i & 31;
            *(float4*)&Ws[r][c4 * 4] = *(const float4*)&W1[(size_t)(kt + r) * DIM + c4 * 4];
        }
        __syncthreads();
#pragma unroll
        for (int k = 0; k < 32; k++) {
            float4 w = *(float4*)&Ws[k][tx * 4];
#pragma unroll
            for (int r = 0; r < 4; r++) {
                float a = As[ty * 4 + r][kt + k];
                acc[r][0] += a * w.x;
                acc[r][1] += a * w.y;
                acc[r][2] += a * w.z;
                acc[r][3] += a * w.w;
            }
        }
        __syncthreads();
    }
    {
        float4 b = *(const float4*)&b1[tx * 4];
        __syncthreads();
#pragma unroll
        for (int r = 0; r < 4; r++) {
            float v0 = fmaxf(acc[r][0] + b.x, 0.f);
            float v1 = fmaxf(acc[r][1] + b.y, 0.f);
            float v2 = fmaxf(acc[r][2] + b.z, 0.f);
            float v3 = fmaxf(acc[r][3] + b.w, 0.f);
            *(float4*)&As[ty * 4 + r][tx * 4] = make_float4(v0, v1, v2, v3);
        }
        __syncthreads();
    }

#pragma unroll
    for (int r = 0; r < 4; r++)
#pragma unroll
        for (int c = 0; c < 4; c++) acc[r][c] = 0.f;
    for (int kt = 0; kt < DIM; kt += 32) {
#pragma unroll
        for (int it = 0; it < 4; it++) {
            int i = tid + it * 256;
            int r = i >> 5, c4 = i & 31;
            *(float4*)&Ws[r][c4 * 4] = *(const float4*)&W2[(size_t)(kt + r) * DIM + c4 * 4];
        }
        __syncthreads();
#pragma unroll
        for (int k = 0; k < 32; k++) {
            float4 w = *(float4*)&Ws[k][tx * 4];
#pragma unroll
            for (int r = 0; r < 4; r++) {
                float a = As[ty * 4 + r][kt + k];
                acc[r][0] += a * w.x;
                acc[r][1] += a * w.y;
                acc[r][2] += a * w.z;
                acc[r][3] += a * w.w;
            }
        }
        __syncthreads();
    }
    {
        float4 b = *(const float4*)&b2[tx * 4];
#pragma unroll
        for (int r = 0; r < 4; r++) {
            int row = row0 + ty * 4 + r;
            float v0 = fmaxf(acc[r][0] + b.x, 0.f);
            float v1 = fmaxf(acc[r][1] + b.y, 0.f);
            float v2 = fmaxf(acc[r][2] + b.z, 0.f);
            float v3 = fmaxf(acc[r][3] + b.w, 0.f);
            *(float4*)&out[(size_t)row * DIM + tx * 4] = make_float4(v0, v1, v2, v3);
        }
    }
}

// ---------------- head GEMM fp32 (FROZEN, small M) -------------------------
__global__ __launch_bounds__(256) void k_gemm(
        const float* __restrict__ A, const float* __restrict__ W,
        const float* __restrict__ bias, float* __restrict__ out,
        int M, int doRelu) {
    __shared__ float As[64][32];
    __shared__ float Ws[32][128];
    int tid = threadIdx.x;
    int tx = tid & 31, ty = tid >> 5;
    int row0 = blockIdx.x * 64;
    float acc[8][4];
#pragma unroll
    for (int r = 0; r < 8; r++)
#pragma unroll
        for (int c = 0; c < 4; c++) acc[r][c] = 0.f;

    for (int kt = 0; kt < DIM; kt += 32) {
#pragma unroll
        for (int it = 0; it < 2; it++) {
            int i = tid + it * 256;
            int r = i >> 3, c4 = i & 7;
            int row = row0 + r;
            float4 v = make_float4(0.f, 0.f, 0.f, 0.f);
            if (row < M) v = *(const float4*)&A[row * DIM + kt + c4 * 4];
            *(float4*)&As[r][c4 * 4] = v;
        }
#pragma unroll
        for (int it = 0; it < 4; it++) {
            int i = tid + it * 256;
            int r = i >> 5, c4 = i & 31;
            *(float4*)&Ws[r][c4 * 4] = *(const float4*)&W[(kt + r) * DIM + c4 * 4];
        }
        __syncthreads();
#pragma unroll
        for (int k = 0; k < 32; k++) {
            float4 w = *(float4*)&Ws[k][tx * 4];
#pragma unroll
            for (int r = 0; r < 8; r++) {
                float a = As[ty * 8 + r][k];
                acc[r][0] += a * w.x;
                acc[r][1] += a * w.y;
                acc[r][2] += a * w.z;
                acc[r][3] += a * w.w;
            }
        }
        __syncthreads();
    }
    float4 b = *(const float4*)&bias[tx * 4];
#pragma unroll
    for (int r = 0; r < 8; r++) {
        int row = row0 + ty * 8 + r;
        if (row < M) {
            float v0 = acc[r][0] + b.x;
            float v1 = acc[r][1] + b.y;
            float v2 = acc[r][2] + b.z;
            float v3 = acc[r][3] + b.w;
            if (doRelu) {
                v0 = fmaxf(v0, 0.f); v1 = fmaxf(v1, 0.f);
                v2 = fmaxf(v2, 0.f); v3 = fmaxf(v3, 0.f);
            }
            *(float4*)&out[row * DIM + tx * 4] = make_float4(v0, v1, v2, v3);
        }
    }
}

// ---------------- BN stats (FROZEN) ---------------------------------------
__global__ void k_stats(const float* __restrict__ t2, float* __restrict__ pstats) {
    __shared__ float ss[256], qq[256];
    int tid = threadIdx.x;
    int col = tid & 127, half = tid >> 7;
    float s = 0.f, q = 0.f;
    int row0 = blockIdx.x * 128;
    for (int i = half; i < 128; i += 2) {
        int r = row0 + i;
        if (r < N_NODES) {
            float v = t2[(size_t)r * DIM + col];
            s += v; q += v * v;
        }
    }
    ss[tid] = s; qq[tid] = q;
    __syncthreads();
    if (tid < 128) {
        pstats[blockIdx.x * 256 + tid]       = ss[tid] + ss[tid + 128];
        pstats[blockIdx.x * 256 + 128 + tid] = qq[tid] + qq[tid + 128];
    }
}

__global__ void k_bnfin(const float* __restrict__ pstats,
                        float* __restrict__ mean, float* __restrict__ invstd) {
    int d = threadIdx.x;
    float s = 0.f, q = 0.f;
    for (int b = 0; b < STAT_BLOCKS; b++) {
        s += pstats[b * 256 + d];
        q += pstats[b * 256 + 128 + d];
    }
    float mu = s / (float)N_NODES;
    float var = q / (float)N_NODES - mu * mu;
    mean[d] = mu;
    invstd[d] = rsqrtf(var + BN_EPS);
}

__global__ void k_bnapply(const float* __restrict__ z, const float* __restrict__ mean,
                          const float* __restrict__ invstd, const float* __restrict__ gamma,
                          const float* __restrict__ beta, float* __restrict__ h) {
    int i = blockIdx.x * blockDim.x + threadIdx.x;
    if (i < N_NODES * DIM) {
        int d = i & (DIM - 1);
        h[i] = (z[i] - mean[d]) * invstd[d] * gamma[d] + beta[d];
    }
}

// ---------------- codebook prep: norms + fp16 split, one pass -------------
__global__ void k_cbprep(const float* __restrict__ cb, float* __restrict__ cnorm,
                         __half* __restrict__ cbs) {
    int warp = (blockIdx.x * blockDim.x + threadIdx.x) >> 5;
    int lane = threadIdx.x & 31;
    if (warp >= CODEBOOK_PAD) return;
    __half* row = cbs + (size_t)warp * VQ_K;
    if (warp >= CODEBOOK_N) {
        if (lane == 0) cnorm[warp] = 1e30f;
        *(ull*)&row[lane * 4] = 0ull;
        *(ull*)&row[128 + lane * 4] = 0ull;
        return;
    }
    float4 v = ((const float4*)cb)[warp * 32 + lane];
    __half hx, lx, hy, ly, hz, lz, hw, lw;
    split16(v.x, hx, lx); split16(v.y, hy, ly);
    split16(v.z, hz, lz); split16(v.w, hw, lw);
    row[lane * 4 + 0] = hx; row[lane * 4 + 1] = hy;
    row[lane * 4 + 2] = hz; row[lane * 4 + 3] = hw;
    row[128 + lane * 4 + 0] = lx; row[128 + lane * 4 + 1] = ly;
    row[128 + lane * 4 + 2] = lz; row[128 + lane * 4 + 3] = lw;
    float s = v.x * v.x + v.y * v.y + v.z * v.z + v.w * v.w;
#pragma unroll
    for (int o = 16; o; o >>= 1) s += __shfl_xor_sync(0xffffffffu, s, o);
    if (lane == 0) cnorm[warp] = s;
}

// ---------------- VQ main: segment-split fp16 3-term GEMM-argmin -----------
__global__ __launch_bounds__(256, 2) void k_vq_mma(
        const float* __restrict__ h, const __half* __restrict__ cbs,
        const float* __restrict__ cnorm,
        float* __restrict__ pd1, float* __restrict__ pd2, int* __restrict__ pj1) {
    extern __shared__ __align__(16) char dyn[];
    __half* As = (__half*)dyn;                 // [64][264]
    __half* Bs = As + 64 * AS_STRIDE;          // [4][64][72]
    float* cns = (float*)(Bs + 4 * BS_BUF_H);  // [64]
    float* rD1 = cns + 64;                     // [64][4]
    float* rD2 = rD1 + 256;
    int*   rJ1 = (int*)(rD2 + 256);
    uint32_t As_u = smem_u32(As);
    uint32_t Bs_u = smem_u32(Bs);

    int tid = threadIdx.x, lane = tid & 31, wid = tid >> 5;
    int warp_m = wid & 1, warp_n = wid >> 1;   // 2m x 4n
    int node0 = blockIdx.x * 64;
    int seg = blockIdx.y;
    int cstart = seg * VQ_CPS;
    int cend = cstart + VQ_CPS;

    {
        int r = tid >> 2, q = tid & 3;
        bool valid = (node0 + r) < N_NODES;
        const float4* hp = (const float4*)(h + (size_t)(valid ? node0 + r : 0) * DIM);
        __half* arow = As + r * AS_STRIDE;
#pragma unroll
        for (int v = 0; v < 8; v++) {
            float4 f = valid ? hp[q * 8 + v] : make_float4(0.f, 0.f, 0.f, 0.f);
            __half hx, lx, hy, ly, hz, lz, hw, lw;
            split16(f.x, hx, lx); split16(f.y, hy, ly);
            split16(f.z, hz, lz); split16(f.w, hw, lw);
            int col = q * 32 + v * 4;
            arow[col + 0] = hx; arow[col + 1] = hy; arow[col + 2] = hz; arow[col + 3] = hw;
            arow[128 + col + 0] = lx; arow[128 + col + 1] = ly;
            arow[128 + col + 2] = lz; arow[128 + col + 3] = lw;
        }
    }

#pragma unroll
    for (int pc = 0; pc < 2; pc++) {
        int ci = cstart + pc;
        const __half* base = cbs + (size_t)(ci >> 2) * 64 * VQ_K + (ci & 3) * 64;
#pragma unroll
        for (int it = 0; it < 2; it++) {
            int i = tid + it * 256;
            int row = i >> 3, c16 = i & 7;
            CP_ASYNC16(Bs_u + (uint32_t)(pc * BS_BUF_H + row * BS_STRIDE + c16 * 8) * 2,
                       base + (size_t)row * VQ_K + c16 * 8);
        }
        CP_COMMIT();
    }

    float d1v[2][2] = {{1e38f, 1e38f}, {1e38f, 1e38f}};
    float d2v[2][2] = {{1e38f, 1e38f}, {1e38f, 1e38f}};
    int   j1v[2][2] = {{0, 0}, {0, 0}};
    int lr = lane & 7, g = lane >> 3;
    float acc[2][2][4];

    for (int ci = cstart; ci < cend; ci++) {
        int t = ci >> 2, c = ci & 3;
        int buf = ci & 3;
        if (c == 0) {
#pragma unroll
            for (int mt = 0; mt < 2; mt++)
#pragma unroll
                for (int hf = 0; hf < 2; hf++)
#pragma unroll
                    for (int r = 0; r < 4; r++) acc[mt][hf][r] = 0.f;
        }
        if (ci + 2 < cend) {
            int pidx = ci + 2;
            int pbuf = pidx & 3;
            const __half* base = cbs + (size_t)(pidx >> 2) * 64 * VQ_K + (pidx & 3) * 64;
#pragma unroll
            for (int it = 0; it < 2; it++) {
                int i = tid + it * 256;
                int row = i >> 3, c16 = i & 7;
                CP_ASYNC16(Bs_u + (uint32_t)(pbuf * BS_BUF_H + row * BS_STRIDE + c16 * 8) * 2,
                           base + (size_t)row * VQ_K + c16 * 8);
            }
            CP_COMMIT();
            CP_WAIT(2);
        } else {
            CP_WAIT(0);
        }
        __syncthreads();
        if (c == 0 && tid < 64) cns[tid] = __ldg(&cnorm[t * 64 + tid]);

        uint32_t bbase = Bs_u + (uint32_t)(buf * BS_BUF_H) * 2;
        if (c < 2) {
#pragma unroll
            for (int kk = 0; kk < 4; kk++) {
                int kcol = c * 64 + kk * 16;
                uint32_t ah0[2], ah1[2], ah2[2], ah3[2];
                uint32_t al0[2], al1[2], al2[2], al3[2];
#pragma unroll
                for (int mt = 0; mt < 2; mt++) {
                    uint32_t abase = As_u +
                        (uint32_t)((warp_m * 32 + mt * 16 + lr + ((g & 1) << 3)) * AS_STRIDE
                                   + kcol + ((g >> 1) << 3)) * 2;
                    LDSM4(ah0[mt], ah1[mt], ah2[mt], ah3[mt], abase);
                    LDSM4(al0[mt], al1[mt], al2[mt], al3[mt], abase + 128 * 2);
                }
                uint32_t b0, b1, b2, b3;
                uint32_t baddr = bbase +
                    (uint32_t)((warp_n * 16 + lr + ((g >> 1) << 3)) * BS_STRIDE
                               + kk * 16 + ((g & 1) << 3)) * 2;
                LDSM4(b0, b1, b2, b3, baddr);
#pragma unroll
                for (int mt = 0; mt < 2; mt++) {
                    MMA16816(acc[mt][0], ah0[mt], ah1[mt], ah2[mt], ah3[mt], b0, b1);
                    MMA16816(acc[mt][1], ah0[mt], ah1[mt], ah2[mt], ah3[mt], b2, b3);
                    MMA16816(acc[mt][0], al0[mt], al1[mt], al2[mt], al3[mt], b0, b1);
                    MMA16816(acc[mt][1], al0[mt], al1[mt], al2[mt], al3[mt], b2, b3);
                }
            }
        } else {
            int cc = c - 2;
#pragma unroll
            for (int kk = 0; kk < 4; kk++) {
                int kcol = cc * 64 + kk * 16;
                uint32_t ah0[2], ah1[2], ah2[2], ah3[2];
#pragma unroll
                for (int mt = 0; mt < 2; mt++) {
                    uint32_t abase = As_u +
                        (uint32_t)((warp_m * 32 + mt * 16 + lr + ((g & 1) << 3)) * AS_STRIDE
                                   + kcol + ((g >> 1) << 3)) * 2;
                    LDSM4(ah0[mt], ah1[mt], ah2[mt], ah3[mt], abase);
                }
                uint32_t b0, b1, b2, b3;
                uint32_t baddr = bbase +
                    (uint32_t)((warp_n * 16 + lr + ((g >> 1) << 3)) * BS_STRIDE
                               + kk * 16 + ((g & 1) << 3)) * 2;
                LDSM4(b0, b1, b2, b3, baddr);
#pragma unroll
                for (int mt = 0; mt < 2; mt++) {
                    MMA16816(acc[mt][0], ah0[mt], ah1[mt], ah2[mt], ah3[mt], b0, b1);
                    MMA16816(acc[mt][1], ah0[mt], ah1[mt], ah2[mt], ah3[mt], b2, b3);
                }
            }
        }

        if (c == VQ_CPT - 1) {
            int cb0 = warp_n * 16;
            int lcol = 2 * (lane & 3);
#pragma unroll
            for (int hf = 0; hf < 2; hf++) {
                int cloc = cb0 + hf * 8 + lcol;
                float cn0 = cns[cloc], cn1 = cns[cloc + 1];
                int code = t * 64 + cloc;
#pragma unroll
                for (int mt = 0; mt < 2; mt++)
#pragma unroll
                    for (int rs = 0; rs < 2; rs++) {
                        float dA = cn0 - 2.f * acc[mt][hf][rs * 2 + 0];
                        float dB = cn1 - 2.f * acc[mt][hf][rs * 2 + 1];
                        if (dA < d1v[mt][rs]) { d2v[mt][rs] = d1v[mt][rs]; d1v[mt][rs] = dA; j1v[mt][rs] = code; }
                        else if (dA < d2v[mt][rs]) d2v[mt][rs] = dA;
                        if (dB < d1v[mt][rs]) { d2v[mt][rs] = d1v[mt][rs]; d1v[mt][rs] = dB; j1v[mt][rs] = code + 1; }
                        else if (dB < d2v[mt][rs]) d2v[mt][rs] = dB;
                    }
            }
        }
    }

#pragma unroll
    for (int o = 1; o <= 2; o <<= 1) {
#pragma unroll
        for (int mt = 0; mt < 2; mt++)
#pragma unroll
            for (int rs = 0; rs < 2; rs++) {
                float od1 = __shfl_xor_sync(0xffffffffu, d1v[mt][rs], o);
                float od2 = __shfl_xor_sync(0xffffffffu, d2v[mt][rs], o);
                int   oj  = __shfl_xor_sync(0xffffffffu, j1v[mt][rs], o);
                if (od1 < d1v[mt][rs] || (od1 == d1v[mt][rs] && oj < j1v[mt][rs])) {
                    d2v[mt][rs] = fminf(d1v[mt][rs], od2);
                    d1v[mt][rs] = od1; j1v[mt][rs] = oj;
                } else {
                    d2v[mt][rs] = fminf(d2v[mt][rs], od1);
                }
            }
    }
    __syncthreads();
    if ((lane & 3) == 0) {
#pragma unroll
        for (int mt = 0; mt < 2; mt++)
#pragma unroll
            for (int rs = 0; rs < 2; rs++) {
                int nl = warp_m * 32 + mt * 16 + rs * 8 + (lane >> 2);
                rD1[nl * 4 + warp_n] = d1v[mt][rs];
                rD2[nl * 4 + warp_n] = d2v[mt][rs];
                rJ1[nl * 4 + warp_n] = j1v[mt][rs];
            }
    }
    __syncthreads();
    if (tid < 64) {
        float f1 = rD1[tid * 4], f2 = rD2[tid * 4];
        int fj = rJ1[tid * 4];
#pragma unroll
        for (int wn = 1; wn < 4; wn++) {
            float b1 = rD1[tid * 4 + wn], b2 = rD2[tid * 4 + wn];
            int bj = rJ1[tid * 4 + wn];
            if (b1 < f1 || (b1 == f1 && bj < fj)) {
                f2 = fminf(f1, b2); f1 = b1; fj = bj;
            } else {
                f2 = fminf(f2, b1);
            }
        }
        int slot = seg * NODE_PAD + node0 + tid;
        pd1[slot] = f1; pd2[slot] = f2; pj1[slot] = fj;
    }
}

// ---------------- merge segments (deterministic, fixed order) --------------
__global__ void k_vqmerge(const float* __restrict__ pd1, const float* __restrict__ pd2,
                          const int* __restrict__ pj1, int* __restrict__ outidx,
                          int* __restrict__ flaglist, int* __restrict__ flagcnt) {
    int n = blockIdx.x * blockDim.x + threadIdx.x;
    if (n >= N_NODES) return;
    float f1 = pd1[n], f2 = pd2[n];
    int fj = pj1[n];
#pragma unroll
    for (int s = 1; s < VQ_SEGS; s++) {
        float b1 = pd1[s * NODE_PAD + n], b2 = pd2[s * NODE_PAD + n];
        int bj = pj1[s * NODE_PAD + n];
        if (b1 < f1 || (b1 == f1 && bj < fj)) {
            f2 = fminf(f1, b2); f1 = b1; fj = bj;
        } else {
            f2 = fminf(f2, b1);
        }
    }
    outidx[n] = fj;
    if (f2 - f1 < VQ_MARGIN) {
        int p = atomicAdd(flagcnt, 1);
        flaglist[p] = n;
    }
}

// ---------------- exact fp32 rescue (order-invariant via atomicMin) --------
__global__ __launch_bounds__(128) void k_rescue(
        const float* __restrict__ h, const float* __restrict__ cb,
        const float* __restrict__ cnorm, const int* __restrict__ flaglist,
        const int* __restrict__ flagcnt, ull* __restrict__ best) {
    extern __shared__ __align__(16) float rs[];
    float* cs   = rs;
    float* hrow = cs + 128 * 128;
    float* rd   = hrow + 128;
    int*   rj   = (int*)(rd + 128);
    int tid = threadIdx.x;
    int c0 = blockIdx.x * 128;
    int code = c0 + tid;
#pragma unroll
    for (int it = 0; it < 32; it++) {
        int i = tid + it * 128;
        int row = i >> 5, c4 = i & 31;
        float4 v = make_float4(0.f, 0.f, 0.f, 0.f);
        if (c0 + row < CODEBOOK_N) v = __ldg(&((const float4*)cb)[(size_t)(c0 + row) * 32 + c4]);
        *(float4*)&cs[row * 128 + c4 * 4] = v;
    }
    float cn = cnorm[code];
    __syncthreads();
    int cnt = *flagcnt;
    const float4* crow4 = (const float4*)&cs[tid * 128];
    const float4* h4 = (const float4*)hrow;
    for (int f = 0; f < cnt; f++) {
        int node = flaglist[f];
        if (tid < 32) ((float4*)hrow)[tid] = ((const float4*)(h + (size_t)node * DIM))[tid];
        __syncthreads();
        float dot = 0.f;
#pragma unroll
        for (int k4 = 0; k4 < 32; k4++) {
            int i = (k4 + tid) & 31;
            float4 cv = crow4[i];
            float4 hv = h4[i];
            dot += cv.x * hv.x + cv.y * hv.y + cv.z * hv.z + cv.w * hv.w;
        }
        float d = cn - 2.f * dot;
        rd[tid] = d; rj[tid] = code;
        __syncthreads();
        for (int o = 64; o; o >>= 1) {
            if (tid < o) {
                float od = rd[tid + o]; int oc = rj[tid + o];
                if (od < rd[tid] || (od == rd[tid] && oc < rj[tid])) {
                    rd[tid] = od; rj[tid] = oc;
                }
            }
            __syncthreads();
        }
        if (tid == 0) {
            ull key = ((ull)fkey(rd[0]) << 32) | (uint32_t)rj[0];
            atomicMin(&best[node], key);
        }
        __syncthreads();
    }
}

__global__ void k_flagapply(const int* __restrict__ flaglist, const int* __restrict__ flagcnt,
                            const ull* __restrict__ best, int* __restrict__ outidx) {
    int cnt = *flagcnt;
    for (int i = blockIdx.x * blockDim.x + threadIdx.x; i < cnt; i += gridDim.x * blockDim.x) {
        int node = flaglist[i];
        outidx[node] = (int)(best[node] & 0xFFFFFFFFull);
    }
}

// ---------------- final per-node ----------------
__global__ void k_final(const float* __restrict__ h, const float* __restrict__ cb,
                        const int* __restrict__ idx, const float* __restrict__ score,
                        const int* __restrict__ batch, float* __restrict__ cacc,
                        float* __restrict__ sacc, float* __restrict__ cmt) {
    __shared__ float sh[256];
    int i = blockIdx.x * blockDim.x + threadIdx.x;
    float local = 0.f;
    if (i < N_NODES * DIM) {
        int node = i >> 7, d = i & 127;
        float hv = h[i];
        float q = cb[idx[node] * DIM + d];
        float diff = q - hv;
        local = diff * diff;
        float res = hv + q;
        float sc = score[node];
        int b = batch[node];
        atomicAdd(&cacc[b * DIM + d], res * sc);
        atomicAdd(&sacc[b * DIM + d], res * (1.f - sc));
    }
    sh[threadIdx.x] = local;
    __syncthreads();
    for (int o = 128; o; o >>= 1) {
        if (threadIdx.x < o) sh[threadIdx.x] += sh[threadIdx.x + o];
        __syncthreads();
    }
    if (threadIdx.x == 0) atomicAdd(cmt, sh[0]);
}

__global__ void k_cmtfin(const float* __restrict__ cmt, float* __restrict__ out) {
    out[2 * N_GRAPHS * DIM] = COMMIT_W * cmt[0] / (float)(N_NODES * DIM);
}

// ---------------- launcher ----------------
extern "C" void kernel_launch(void* const* d_in, const int* in_sizes, int n_in,
                              void* d_out, int out_size) {
    const float* x        = (const float*)d_in[0];
    const int*   ei       = (const int*)  d_in[1];
    const int*   batch    = (const int*)  d_in[2];
    const float* score    = (const float*)d_in[3];
    const float* cW1      = (const float*)d_in[4];
    const float* cb1      = (const float*)d_in[5];
    const float* cW2      = (const float*)d_in[6];
    const float* cb2      = (const float*)d_in[7];
    const float* bng      = (const float*)d_in[8];
    const float* bnb      = (const float*)d_in[9];
    const float* codebook = (const float*)d_in[10];
    const float* fc1W     = (const float*)d_in[11];
    const float* fc1b     = (const float*)d_in[12];
    const float* fc2W     = (const float*)d_in[13];
    const float* fc2b     = (const float*)d_in[14];
    float* out = (float*)d_out;
    const int* src = ei;
    const int* dst = ei + N_EDGES;

    void *p_z, *p_t2, *p_h, *p_deg, *p_offs, *p_cursor, *p_csrk;
    void *p_pstats, *p_mean, *p_invstd, *p_cnorm, *p_idx, *p_cacc, *p_sacc, *p_cmt;
    void *p_cbs, *p_pd1, *p_pd2, *p_pj1, *p_flag, *p_fcnt, *p_best;
    cudaGetSymbolAddress(&p_z, g_z);
    cudaGetSymbolAddress(&p_t2, g_t2);
    cudaGetSymbolAddress(&p_h, g_h);
    cudaGetSymbolAddress(&p_deg, g_deg);
    cudaGetSymbolAddress(&p_offs, g_offs);
    cudaGetSymbolAddress(&p_cursor, g_cursor);
    cudaGetSymbolAddress(&p_csrk, g_csrk);
    cudaGetSymbolAddress(&p_pstats, g_pstats);
    cudaGetSymbolAddress(&p_mean, g_mean);
    cudaGetSymbolAddress(&p_invstd, g_invstd);
    cudaGetSymbolAddress(&p_cnorm, g_cnorm);
    cudaGetSymbolAddress(&p_idx, g_idx);
    cudaGetSymbolAddress(&p_cacc, g_cacc);
    cudaGetSymbolAddress(&p_sacc, g_sacc);
    cudaGetSymbolAddress(&p_cmt, g_cmt);
    cudaGetSymbolAddress(&p_cbs, g_cbs);
    cudaGetSymbolAddress(&p_pd1, g_pd1);
    cudaGetSymbolAddress(&p_pd2, g_pd2);
    cudaGetSymbolAddress(&p_pj1, g_pj1);
    cudaGetSymbolAddress(&p_flag, g_flaglist);
    cudaGetSymbolAddress(&p_fcnt, g_flagcnt);
    cudaGetSymbolAddress(&p_best, g_best);

    const int SMEM_VQ = 64 * AS_STRIDE * 2 + 4 * BS_BUF_H * 2 + 64 * 4 + 256 * 4 * 3;
    const int SMEM_RESCUE = 128 * 128 * 4 + 128 * 4 * 3;
    static bool attr_set = false;
    if (!attr_set) {
        cudaFuncSetAttribute(k_vq_mma, cudaFuncAttributeMaxDynamicSharedMemorySize, SMEM_VQ);
        cudaFuncSetAttribute(k_rescue, cudaFuncAttributeMaxDynamicSharedMemorySize, SMEM_RESCUE);
        attr_set = true;
    }

    // CSR build, canonicalized to exact EDGE order (FROZEN)
    cudaMemsetAsync(p_deg, 0, N_NODES * sizeof(int));
    k_hist<<<(N_EDGES + 255) / 256, 256>>>(dst, (int*)p_deg);
    k_scan<<<1, 1024>>>((const int*)p_deg, (int*)p_offs);
    cudaMemcpyAsync(p_cursor, p_offs, N_NODES * sizeof(int), cudaMemcpyDeviceToDevice);
    k_fill<<<(N_EDGES + 255) / 256, 256>>>(src, dst, (int*)p_cursor, (ull*)p_csrk);
    k_sortcsr<<<(N_NODES + 127) / 128, 128>>>((const int*)p_offs, (ull*)p_csrk);

    // codebook prep (one pass: norm + fp16 split)
    k_cbprep<<<(CODEBOOK_PAD * 32 + 255) / 256, 256>>>(codebook, (float*)p_cnorm,
                                                       (__half*)p_cbs);

    // MLP chain: R14-proven structure (h bitwise identical)
    const float* h = x;
    for (int l = 0; l < N_LAYERS; l++) {
        k_agg<<<(N_NODES * 32 + 255) / 256, 256>>>(h, (const int*)p_offs,
                                                   (const ull*)p_csrk, (float*)p_z);
        k_gemm_fused<<<N_NODES / 32, 256>>>(
            (const float*)p_z, cW1 + l * DIM * DIM, cb1 + l * DIM,
            cW2 + l * DIM * DIM, cb2 + l * DIM, (float*)p_t2);
        k_stats<<<STAT_BLOCKS, 256>>>((const float*)p_t2, (float*)p_pstats);
        k_bnfin<<<1, 128>>>((const float*)p_pstats, (float*)p_mean, (float*)p_invstd);
        k_bnapply<<<(N_NODES * DIM + 255) / 256, 256>>>(
            (const float*)p_t2, (const float*)p_mean, (const float*)p_invstd,
            bng + l * DIM, bnb + l * DIM, (float*)p_h);
        h = (const float*)p_h;
    }

    // VQ: segment-split tensor-core search + deterministic merge + exact rescue
    cudaMemsetAsync(p_fcnt, 0, sizeof(int));
    cudaMemsetAsync(p_best, 0xFF, N_NODES * sizeof(ull));
    k_vq_mma<<<dim3(VQ_MBLK, VQ_SEGS), 256, SMEM_VQ>>>(
        (const float*)p_h, (const __half*)p_cbs, (const float*)p_cnorm,
        (float*)p_pd1, (float*)p_pd2, (int*)p_pj1);
    k_vqmerge<<<(N_NODES + 255) / 256, 256>>>(
        (const float*)p_pd1, (const float*)p_pd2, (const int*)p_pj1,
        (int*)p_idx, (int*)p_flag, (int*)p_fcnt);
    k_rescue<<<CODEBOOK_PAD / 128, 128, SMEM_RESCUE>>>(
        (const float*)p_h, codebook, (const float*)p_cnorm,
        (const int*)p_flag, (const int*)p_fcnt, (ull*)p_best);
    k_flagapply<<<40, 256>>>((const int*)p_flag, (const int*)p_fcnt,
                             (const ull*)p_best, (int*)p_idx);

    cudaMemsetAsync(p_cacc, 0, N_GRAPHS * DIM * sizeof(float));
    cudaMemsetAsync(p_sacc, 0, N_GRAPHS * DIM * sizeof(float));
    cudaMemsetAsync(p_cmt, 0, sizeof(float));
    k_final<<<(N_NODES * DIM + 255) / 256, 256>>>(
        (const float*)p_h, codebook, (const int*)p_idx, score, batch,
        (float*)p_cacc, (float*)p_sacc, (float*)p_cmt);

    k_gemm<<<(N_GRAPHS + 63) / 64, 256>>>((const float*)p_cacc, fc1W, fc1b,
                                          out, N_GRAPHS, 1);
    k_gemm<<<(N_GRAPHS + 63) / 64, 256>>>((const float*)p_sacc, fc2W, fc2b,
                                          out + N_GRAPHS * DIM, N_GRAPHS, 1);
    k_cmtfin<<<1, 1>>>((const float*)p_cmt, out);
}